// round 7
// baseline (speedup 1.0000x reference)
#include <cuda_runtime.h>
#include <cuda_bf16.h>
#include <math.h>

typedef unsigned long long u64;

__device__ __forceinline__ u64 pack2(float lo, float hi) {
    u64 r; asm("mov.b64 %0,{%1,%2};" : "=l"(r) : "f"(lo), "f"(hi)); return r;
}
__device__ __forceinline__ void unpack2(u64 v, float& lo, float& hi) {
    asm("mov.b64 {%0,%1},%2;" : "=f"(lo), "=f"(hi) : "l"(v));
}
__device__ __forceinline__ u64 fma2(u64 a, u64 b, u64 c) {
    u64 d; asm("fma.rn.f32x2 %0,%1,%2,%3;" : "=l"(d) : "l"(a), "l"(b), "l"(c)); return d;
}
__device__ __forceinline__ unsigned to_tf32(float x) {
    unsigned r; asm("cvt.rna.tf32.f32 %0,%1;" : "=r"(r) : "f"(x)); return r;
}
__device__ __forceinline__ void mma8(float c[4],
    unsigned a0, unsigned a1, unsigned a2, unsigned a3,
    unsigned b0, unsigned b1)
{
    asm volatile(
        "mma.sync.aligned.m16n8k8.row.col.f32.tf32.tf32.f32 "
        "{%0,%1,%2,%3},{%4,%5,%6,%7},{%8,%9},{%0,%1,%2,%3};"
        : "+f"(c[0]), "+f"(c[1]), "+f"(c[2]), "+f"(c[3])
        : "r"(a0), "r"(a1), "r"(a2), "r"(a3), "r"(b0), "r"(b1));
}

// ---------------- scratch (device globals; no allocations) ----------------
__device__ float g_bufA[4u * 256u * 64u * 64u];
__device__ float g_bufB[4u * 256u * 64u * 64u];
__device__ float g_warp[4 * 2 * 64 * 64];
__device__ float g_stats[1024];                   // [mean(C) | rsqrt(var+eps)(C)]

// ---------------------------------------------------------------------------
// Kernel 1: fused correlation + softmax + expected grid position (f32x2 GEMM)
// ---------------------------------------------------------------------------
__global__ __launch_bounds__(128) void corr_kernel(
    const float* __restrict__ f0, const float* __restrict__ f1,
    float* __restrict__ warp)
{
    const int b  = blockIdx.x >> 7;
    const int p0 = (blockIdx.x & 127) * 32;

    __shared__ __align__(16) float f0_s[64][32];
    __shared__ __align__(16) float f1_sc[64 * 128];
    __shared__ float m_s[32], l_s[32], sx_s[32], sy_s[32];

    const int t    = threadIdx.x;
    const int tx   = t & 15;
    const int ty   = t >> 4;
    const int q    = t >> 2;
    const int quad = t & 3;

    for (int i = t; i < 64 * 32; i += 128) {
        int p = i & 31, c = i >> 5;
        f0_s[c][p] = f0[(b * 64 + c) * 4096 + p0 + p];
    }
    if (t < 32) { m_s[t] = -1e30f; l_s[t] = 0.f; sx_s[t] = 0.f; sy_s[t] = 0.f; }
    __syncthreads();

    for (int j0 = 0; j0 < 4096; j0 += 128) {
        for (int i = t; i < 64 * 128; i += 128) {
            int j = i & 127, c = i >> 7;
            f1_sc[c * 128 + j] = f1[(b * 64 + c) * 4096 + j0 + j];
        }
        __syncthreads();

        u64 acc2[4][4];
        #pragma unroll
        for (int i = 0; i < 4; i++)
            #pragma unroll
            for (int jp = 0; jp < 4; jp++) acc2[i][jp] = 0ull;

        #pragma unroll 16
        for (int c = 0; c < 64; c++) {
            float4 a0 = *(const float4*)&f0_s[c][ty * 4];
            u64 ap[4] = { pack2(a0.x, a0.x), pack2(a0.y, a0.y),
                          pack2(a0.z, a0.z), pack2(a0.w, a0.w) };
            const u64* bp = (const u64*)&f1_sc[c * 128 + tx * 8];
            u64 b0 = bp[0], b1 = bp[1], b2 = bp[2], b3 = bp[3];
            #pragma unroll
            for (int i = 0; i < 4; i++) {
                acc2[i][0] = fma2(ap[i], b0, acc2[i][0]);
                acc2[i][1] = fma2(ap[i], b1, acc2[i][1]);
                acc2[i][2] = fma2(ap[i], b2, acc2[i][2]);
                acc2[i][3] = fma2(ap[i], b3, acc2[i][3]);
            }
        }
        __syncthreads();

        #pragma unroll
        for (int i = 0; i < 4; i++)
            #pragma unroll
            for (int jp = 0; jp < 4; jp++) {
                float lo, hi; unpack2(acc2[i][jp], lo, hi);
                f1_sc[(ty * 4 + i) * 132 + tx * 8 + 2 * jp]     = lo * 0.125f;
                f1_sc[(ty * 4 + i) * 132 + tx * 8 + 2 * jp + 1] = hi * 0.125f;
            }
        __syncthreads();

        float m_old = m_s[q];
        float sc[32];
        float tm = -1e30f;
        #pragma unroll
        for (int i = 0; i < 32; i++) {
            sc[i] = f1_sc[q * 132 + quad + 4 * i];
            tm = fmaxf(tm, sc[i]);
        }
        tm = fmaxf(tm, __shfl_xor_sync(0xffffffffu, tm, 1));
        tm = fmaxf(tm, __shfl_xor_sync(0xffffffffu, tm, 2));
        float nm = fmaxf(m_old, tm);

        float le = 0.f, lx = 0.f, ly = 0.f;
        #pragma unroll
        for (int i = 0; i < 32; i++) {
            int j   = j0 + quad + 4 * i;
            float e = __expf(sc[i] - nm);
            float gx = (float)((j & 63) * 2 + 1) * (1.f / 64.f) - 1.f;
            float gy = (float)((j >> 6) * 2 + 1) * (1.f / 64.f) - 1.f;
            le += e;
            lx = fmaf(e, gx, lx);
            ly = fmaf(e, gy, ly);
        }
        le += __shfl_xor_sync(0xffffffffu, le, 1);
        le += __shfl_xor_sync(0xffffffffu, le, 2);
        lx += __shfl_xor_sync(0xffffffffu, lx, 1);
        lx += __shfl_xor_sync(0xffffffffu, lx, 2);
        ly += __shfl_xor_sync(0xffffffffu, ly, 1);
        ly += __shfl_xor_sync(0xffffffffu, ly, 2);

        if (quad == 0) {
            float s = __expf(m_old - nm);
            l_s[q]  = l_s[q]  * s + le;
            sx_s[q] = sx_s[q] * s + lx;
            sy_s[q] = sy_s[q] * s + ly;
            m_s[q]  = nm;
        }
        __syncthreads();
    }

    if (t < 32) {
        float inv = 1.f / l_s[t];
        warp[(b * 2 + 0) * 4096 + p0 + t] = sx_s[t] * inv;
        warp[(b * 2 + 1) * 4096 + p0 + t] = sy_s[t] * inv;
    }
}

// ---------------------------------------------------------------------------
// Kernel 2: conv3x3 SAME via tensor-core implicit GEMM (3xTF32, ~fp32 acc).
// Block: 256 thr = 8 warps (4 in M x 2 in N). Block tile: 64 co x 128 px
// (8h x 16w). Warp tile: 16 co x 64 px. K chunked by 8 input channels.
// Smem stores hi/lo tf32 split interleaved as float2 (1 LDS.64 per operand).
// Optional BN+ReLU fold on the input (bn = [mean|rstd] of Cin, or nullptr).
// Dyn smem: in_s 8x10x18 float2 (1440) + w_s 9x8x68 float2 (4896) = 50688 B.
// ---------------------------------------------------------------------------
__global__ __launch_bounds__(256) void conv3x3_mma_kernel(
    const float* __restrict__ in, const float* __restrict__ wgt,
    const float* __restrict__ bn, float* __restrict__ out,
    int Cin, int Cout, int H, int W)
{
    extern __shared__ float2 smem[];
    float2* in_s = smem;            // [ci=8][h=10][w=18]
    float2* w_s  = smem + 1440;     // [tap=9][ci=8][co=68pad]

    const int tilesW = W >> 4;
    const int tw = blockIdx.x % tilesW;
    const int th = blockIdx.x / tilesW;
    const int h0 = th * 8, w0 = tw * 16;
    const int b   = blockIdx.y;
    const int cob = blockIdx.z * 64;

    const int t = threadIdx.x;
    const int lane  = t & 31;
    const int warpId = t >> 5;
    const int warpM = warpId & 3;      // 0..3 -> co
    const int warpN = warpId >> 2;     // 0..1 -> pixel half
    const int m0 = warpM * 16;
    const int r = lane >> 2;           // 0..7
    const int c = lane & 3;            // 0..3

    float acc[8][4];
    #pragma unroll
    for (int j = 0; j < 8; j++)
        #pragma unroll
        for (int k = 0; k < 4; k++) acc[j][k] = 0.f;

    const bool hasBN = (bn != nullptr);
    const float* inb = in + (size_t)b * Cin * H * W;

    for (int ci0 = 0; ci0 < Cin; ci0 += 8) {
        __syncthreads();   // protect previous iteration's smem reads

        // ---- stage input tile (with halo + BN fold + tf32 hi/lo split) ----
        for (int i = t; i < 1440; i += 256) {
            int ww = i % 18; int rem = i / 18; int hh = rem % 10; int ci = rem / 10;
            int gh = h0 + hh - 1, gw = w0 + ww - 1, gc = ci0 + ci;
            float v = 0.f;
            if (gc < Cin && (unsigned)gh < (unsigned)H && (unsigned)gw < (unsigned)W) {
                v = inb[(gc * H + gh) * W + gw];
                if (hasBN) v = fmaxf((v - bn[gc]) * bn[Cin + gc], 0.f);
            }
            unsigned hb = to_tf32(v);
            float hf = __uint_as_float(hb);
            unsigned lb = to_tf32(v - hf);
            in_s[i] = make_float2(hf, __uint_as_float(lb));
        }
        // ---- stage weights (tf32 hi/lo split) ----
        for (int i = t; i < 4608; i += 256) {
            int co = i & 63; int rem = i >> 6; int tap = rem % 9; int ci = rem / 9;
            int gc = ci0 + ci;
            float v = (gc < Cin) ? wgt[((cob + co) * Cin + gc) * 9 + tap] : 0.f;
            unsigned hb = to_tf32(v);
            float hf = __uint_as_float(hb);
            unsigned lb = to_tf32(v - hf);
            w_s[tap * 544 + ci * 68 + co] = make_float2(hf, __uint_as_float(lb));
        }
        __syncthreads();

        // ---- compute: 9 taps x 8 n-frags x 3 MMAs (3xTF32) ----
        #pragma unroll
        for (int kh = 0; kh < 3; kh++) {
            #pragma unroll
            for (int kw = 0; kw < 3; kw++) {
                const float2* wb = w_s + (kh * 3 + kw) * 544;
                float2 A0 = wb[c * 68 + m0 + r];
                float2 A1 = wb[c * 68 + m0 + r + 8];
                float2 A2 = wb[(c + 4) * 68 + m0 + r];
                float2 A3 = wb[(c + 4) * 68 + m0 + r + 8];
                unsigned ah0 = __float_as_uint(A0.x), al0 = __float_as_uint(A0.y);
                unsigned ah1 = __float_as_uint(A1.x), al1 = __float_as_uint(A1.y);
                unsigned ah2 = __float_as_uint(A2.x), al2 = __float_as_uint(A2.y);
                unsigned ah3 = __float_as_uint(A3.x), al3 = __float_as_uint(A3.y);

                #pragma unroll
                for (int j = 0; j < 8; j++) {
                    int hl = warpN * 4 + (j >> 1) + kh;
                    int wl = (j & 1) * 8 + r + kw;
                    float2 B0 = in_s[c * 180 + hl * 18 + wl];
                    float2 B1 = in_s[(c + 4) * 180 + hl * 18 + wl];
                    unsigned bh0 = __float_as_uint(B0.x), bl0 = __float_as_uint(B0.y);
                    unsigned bh1 = __float_as_uint(B1.x), bl1 = __float_as_uint(B1.y);
                    mma8(acc[j], ah0, ah1, ah2, ah3, bh0, bh1);
                    mma8(acc[j], al0, al1, al2, al3, bh0, bh1);
                    mma8(acc[j], ah0, ah1, ah2, ah3, bl0, bl1);
                }
            }
        }
    }

    // ---- store: each thread 8 j x 2 float2 ----
    #pragma unroll
    for (int j = 0; j < 8; j++) {
        int h = h0 + warpN * 4 + (j >> 1);
        int w = w0 + (j & 1) * 8 + 2 * c;
        int co0 = cob + m0 + r;
        float* o0 = out + (((size_t)b * Cout + co0) * H + h) * W + w;
        *(float2*)o0 = make_float2(acc[j][0], acc[j][1]);
        float* o1 = out + (((size_t)b * Cout + co0 + 8) * H + h) * W + w;
        *(float2*)o1 = make_float2(acc[j][2], acc[j][3]);
    }
}

// ---------------------------------------------------------------------------
// BN stats: one block per channel; mean & rsqrt(var+eps) over (B,H,W)
// ---------------------------------------------------------------------------
__global__ __launch_bounds__(512) void bnstats_kernel(
    const float* __restrict__ x, float* __restrict__ stats,
    int B_, int C, int HW)
{
    const int c = blockIdx.x;
    const int N = B_ * HW;
    float s = 0.f, sq = 0.f;
    for (int i = threadIdx.x; i < N; i += 512) {
        int b = i / HW, p = i - b * HW;
        float v = x[(b * C + c) * HW + p];
        s += v; sq = fmaf(v, v, sq);
    }
    __shared__ float rs[512], rq[512];
    rs[threadIdx.x] = s; rq[threadIdx.x] = sq;
    __syncthreads();
    for (int off = 256; off > 0; off >>= 1) {
        if (threadIdx.x < off) {
            rs[threadIdx.x] += rs[threadIdx.x + off];
            rq[threadIdx.x] += rq[threadIdx.x + off];
        }
        __syncthreads();
    }
    if (threadIdx.x == 0) {
        float m   = rs[0] / (float)N;
        float var = rq[0] / (float)N - m * m;
        stats[c]     = m;
        stats[C + c] = rsqrtf(var + 1e-5f);
    }
}

__global__ void bnrelu_kernel(float* __restrict__ x, const float* __restrict__ stats,
                              int C, int HW, int total)
{
    int i = blockIdx.x * blockDim.x + threadIdx.x;
    if (i >= total) return;
    int c = (i / HW) % C;
    float v = (x[i] - stats[c]) * stats[C + c];
    x[i] = v > 0.f ? v : 0.f;
}

// ---------------------------------------------------------------------------
// grid_sample (zero padding, bilinear), writes into concat buffer at dstCoff
// ---------------------------------------------------------------------------
__global__ void gridsample_kernel(
    const float* __restrict__ img, const float* __restrict__ coords,
    float* __restrict__ dst, int B_, int C, int H, int W,
    int cStrideB, int gyOff, int dstCtot, int dstCoff)
{
    int idx = blockIdx.x * blockDim.x + threadIdx.x;
    int HW = H * W;
    if (idx >= B_ * C * HW) return;
    int p = idx % HW;
    int c = (idx / HW) % C;
    int b = idx / (HW * C);

    float gx = coords[b * cStrideB + p];
    float gy = coords[b * cStrideB + gyOff + p];
    float x = (gx + 1.f) * (W * 0.5f) - 0.5f;
    float y = (gy + 1.f) * (H * 0.5f) - 0.5f;
    float x0f = floorf(x), y0f = floorf(y);
    float wx = x - x0f, wy = y - y0f;
    int x0 = (int)x0f, y0 = (int)y0f;

    const float* ip = img + (b * C + c) * HW;
    auto samp = [&](int yi, int xi) -> float {
        bool valid = (xi >= 0) && (xi < W) && (yi >= 0) && (yi < H);
        int yc = min(max(yi, 0), H - 1);
        int xc = min(max(xi, 0), W - 1);
        return valid ? ip[yc * W + xc] : 0.f;
    };
    float r = samp(y0,     x0    ) * (1.f - wx) * (1.f - wy)
            + samp(y0,     x0 + 1) * wx         * (1.f - wy)
            + samp(y0 + 1, x0    ) * (1.f - wx) * wy
            + samp(y0 + 1, x0 + 1) * wx         * wy;
    dst[((b * dstCtot) + dstCoff + c) * HW + p] = r;
}

// ---------------------------------------------------------------------------
__global__ void copy_strided_kernel(const float* __restrict__ src, float* __restrict__ dst,
                                    int perB, int srcStride, int dstStride, int B_)
{
    int i = blockIdx.x * blockDim.x + threadIdx.x;
    if (i >= B_ * perB) return;
    int b = i / perB, r = i - b * perB;
    dst[b * dstStride + r] = src[b * srcStride + r];
}

// ---------------------------------------------------------------------------
__global__ void upsample2x_kernel(const float* __restrict__ src, float* __restrict__ dst,
                                  int B_, int C, int Hi, int Wi)
{
    int Ho = Hi * 2, Wo = Wi * 2;
    int idx = blockIdx.x * blockDim.x + threadIdx.x;
    if (idx >= B_ * C * Ho * Wo) return;
    int wo = idx % Wo;
    int ho = (idx / Wo) % Ho;
    int bc = idx / (Wo * Ho);

    float sy = ho * 0.5f - 0.25f;
    float sx = wo * 0.5f - 0.25f;
    float fy = sy - floorf(sy);
    float fx = sx - floorf(sx);
    int y0 = (int)floorf(sy), x0 = (int)floorf(sx);
    int y0c = min(max(y0, 0), Hi - 1), y1c = min(max(y0 + 1, 0), Hi - 1);
    int x0c = min(max(x0, 0), Wi - 1), x1c = min(max(x0 + 1, 0), Wi - 1);

    const float* sp = src + bc * Hi * Wi;
    float v = sp[y0c * Wi + x0c] * (1.f - fy) * (1.f - fx)
            + sp[y0c * Wi + x1c] * (1.f - fy) * fx
            + sp[y1c * Wi + x0c] * fy * (1.f - fx)
            + sp[y1c * Wi + x1c] * fy * fx;
    dst[idx] = v;
}

// ---------------------------------------------------------------------------
__global__ void conv1x1_3_kernel(
    const float* __restrict__ x, const float* __restrict__ w5, const float* __restrict__ b5,
    const float* __restrict__ base, int baseC, int baseStrideB,
    float* __restrict__ out, int Cin, int HW, int B_)
{
    int idx = blockIdx.x * blockDim.x + threadIdx.x;
    if (idx >= B_ * HW) return;
    int b = idx / HW, p = idx - b * HW;

    float a0 = 0.f, a1 = 0.f, a2 = 0.f;
    const float* xp = x + (size_t)b * Cin * HW + p;
    for (int ci = 0; ci < Cin; ci++) {
        float v = xp[(size_t)ci * HW];
        a0 = fmaf(v, __ldg(&w5[ci]),            a0);
        a1 = fmaf(v, __ldg(&w5[Cin + ci]),      a1);
        a2 = fmaf(v, __ldg(&w5[2 * Cin + ci]),  a2);
    }
    float b0v = base[b * baseStrideB + p];
    float b1v = base[b * baseStrideB + HW + p];
    float b2v = (baseC > 2) ? base[b * baseStrideB + 2 * HW + p] : 0.f;

    out[(size_t)b * 3 * HW + p]           = a0 + __ldg(&b5[0]) + b0v;
    out[(size_t)b * 3 * HW + HW + p]      = a1 + __ldg(&b5[1]) + b1v;
    out[(size_t)b * 3 * HW + 2 * HW + p]  = a2 + __ldg(&b5[2]) + b2v;
}

// ---------------------------------------------------------------------------
extern "C" void kernel_launch(void* const* d_in, const int* in_sizes, int n_in,
                              void* d_out, int out_size)
{
    const float* f0c = (const float*)d_in[0];
    const float* f1c = (const float*)d_in[1];
    const float* f0f = (const float*)d_in[2];
    const float* f1f = (const float*)d_in[3];
    const float* cw1 = (const float*)d_in[4];
    const float* cw2 = (const float*)d_in[5];
    const float* cw3 = (const float*)d_in[6];
    const float* cw4 = (const float*)d_in[7];
    const float* cw5 = (const float*)d_in[8];
    const float* cb5 = (const float*)d_in[9];
    const float* fw1 = (const float*)d_in[10];
    const float* fw2 = (const float*)d_in[11];
    const float* fw3 = (const float*)d_in[12];
    const float* fw4 = (const float*)d_in[13];
    const float* fw5 = (const float*)d_in[14];
    const float* fb5 = (const float*)d_in[15];

    float *A, *Bb, *warp, *stats;
    cudaGetSymbolAddress((void**)&A,     g_bufA);
    cudaGetSymbolAddress((void**)&Bb,    g_bufB);
    cudaGetSymbolAddress((void**)&warp,  g_warp);
    cudaGetSymbolAddress((void**)&stats, g_stats);

    const int CONV_SMEM = 6336 * 8;   // 50688 bytes
    cudaFuncSetAttribute(conv3x3_mma_kernel,
                         cudaFuncAttributeMaxDynamicSharedMemorySize, CONV_SMEM);

    float* outC = (float*)d_out;                 // (4,3,64,64)
    float* outF = outC + 4 * 3 * 64 * 64;        // (4,3,128,128)

    const int HWc = 64 * 64, HWf = 128 * 128;

    // ---- coarse stage ----
    corr_kernel<<<512, 128>>>(f0c, f1c, warp);

    copy_strided_kernel<<<(4 * 64 * HWc + 255) / 256, 256>>>(
        f0c, A, 64 * HWc, 64 * HWc, 130 * HWc, 4);
    copy_strided_kernel<<<(4 * 2 * HWc + 255) / 256, 256>>>(
        warp, A + 128 * HWc, 2 * HWc, 2 * HWc, 130 * HWc, 4);
    gridsample_kernel<<<(4 * 64 * HWc + 255) / 256, 256>>>(
        f1c, warp, A, 4, 64, 64, 64, 2 * HWc, HWc, 130, 64);

    dim3 cg(32, 4, 4);   // pxTiles=(64/8)*(64/16)=32, B=4, coBlocks=256/64=4
    conv3x3_mma_kernel<<<cg, 256, CONV_SMEM>>>(A, cw1, nullptr, Bb, 130, 256, 64, 64);
    bnstats_kernel<<<256, 512>>>(Bb, stats, 4, 256, HWc);

    conv3x3_mma_kernel<<<cg, 256, CONV_SMEM>>>(Bb, cw2, stats, A, 256, 256, 64, 64);
    bnstats_kernel<<<256, 512>>>(A, stats, 4, 256, HWc);

    conv3x3_mma_kernel<<<cg, 256, CONV_SMEM>>>(A, cw3, stats, Bb, 256, 256, 64, 64);
    bnstats_kernel<<<256, 512>>>(Bb, stats, 4, 256, HWc);

    conv3x3_mma_kernel<<<cg, 256, CONV_SMEM>>>(Bb, cw4, stats, A, 256, 256, 64, 64);
    bnstats_kernel<<<256, 512>>>(A, stats, 4, 256, HWc);
    bnrelu_kernel<<<(4 * 256 * HWc + 255) / 256, 256>>>(A, stats, 256, HWc, 4 * 256 * HWc);

    conv1x1_3_kernel<<<(4 * HWc + 127) / 128, 128>>>(
        A, cw5, cb5, warp, 2, 2 * HWc, outC, 256, HWc, 4);

    // ---- fine stage ----
    upsample2x_kernel<<<(4 * 3 * HWf + 255) / 256, 256>>>(outC, outF, 4, 3, 64, 64);

    copy_strided_kernel<<<(4 * 24 * HWf + 255) / 256, 256>>>(
        f0f, Bb, 24 * HWf, 24 * HWf, 50 * HWf, 4);
    copy_strided_kernel<<<(4 * 2 * HWf + 255) / 256, 256>>>(
        outF, Bb + 48 * HWf, 2 * HWf, 3 * HWf, 50 * HWf, 4);
    gridsample_kernel<<<(4 * 24 * HWf + 255) / 256, 256>>>(
        f1f, outF, Bb, 4, 24, 128, 128, 3 * HWf, HWf, 50, 24);

    dim3 fg(128, 4, 1);  // pxTiles=(128/8)*(128/16)=128, B=4, coBlocks=1
    conv3x3_mma_kernel<<<fg, 256, CONV_SMEM>>>(Bb, fw1, nullptr, A, 50, 64, 128, 128);
    bnstats_kernel<<<64, 512>>>(A, stats, 4, 64, HWf);

    conv3x3_mma_kernel<<<fg, 256, CONV_SMEM>>>(A, fw2, stats, Bb, 64, 64, 128, 128);
    bnstats_kernel<<<64, 512>>>(Bb, stats, 4, 64, HWf);

    conv3x3_mma_kernel<<<fg, 256, CONV_SMEM>>>(Bb, fw3, stats, A, 64, 64, 128, 128);
    bnstats_kernel<<<64, 512>>>(A, stats, 4, 64, HWf);

    conv3x3_mma_kernel<<<fg, 256, CONV_SMEM>>>(A, fw4, stats, Bb, 64, 64, 128, 128);
    bnstats_kernel<<<64, 512>>>(Bb, stats, 4, 64, HWf);
    bnrelu_kernel<<<(4 * 64 * HWf + 255) / 256, 256>>>(Bb, stats, 64, HWf, 4 * 64 * HWf);

    conv1x1_3_kernel<<<(4 * HWf + 127) / 128, 128>>>(
        Bb, fw5, fb5, outF, 3, 3 * HWf, outF, 64, HWf, 4);
}

// round 8
// speedup vs baseline: 1.6321x; 1.6321x over previous
#include <cuda_runtime.h>
#include <cuda_bf16.h>
#include <math.h>

typedef unsigned long long u64;

__device__ __forceinline__ u64 pack2(float lo, float hi) {
    u64 r; asm("mov.b64 %0,{%1,%2};" : "=l"(r) : "f"(lo), "f"(hi)); return r;
}
__device__ __forceinline__ void unpack2(u64 v, float& lo, float& hi) {
    asm("mov.b64 {%0,%1},%2;" : "=f"(lo), "=f"(hi) : "l"(v));
}
__device__ __forceinline__ u64 fma2(u64 a, u64 b, u64 c) {
    u64 d; asm("fma.rn.f32x2 %0,%1,%2,%3;" : "=l"(d) : "l"(a), "l"(b), "l"(c)); return d;
}

// ---------------- scratch (device globals; no allocations) ----------------
__device__ float g_bufA[4u * 256u * 64u * 64u];     // 16.8 MB
__device__ float g_bufB[4u * 256u * 64u * 64u];     // 16.8 MB
__device__ float g_V[16u * 256u * 4096u];           // 67 MB (Winograd V)
__device__ float g_M[16u * 256u * 4096u];           // 67 MB (Winograd M)
__device__ float g_U[16u * 256u * 256u];            // 4 MB  (Winograd U)
__device__ float g_warp[4 * 2 * 64 * 64];
__device__ float g_stats[1024];                     // [mean(C) | rstd(C)]

// ---------------------------------------------------------------------------
// Kernel 1: fused correlation + softmax + expected grid position
// ---------------------------------------------------------------------------
__global__ __launch_bounds__(128) void corr_kernel(
    const float* __restrict__ f0, const float* __restrict__ f1,
    float* __restrict__ warp)
{
    const int b  = blockIdx.x >> 7;
    const int p0 = (blockIdx.x & 127) * 32;

    __shared__ __align__(16) float f0_s[64][32];
    __shared__ __align__(16) float f1_sc[64 * 128];
    __shared__ float m_s[32], l_s[32], sx_s[32], sy_s[32];

    const int t    = threadIdx.x;
    const int tx   = t & 15;
    const int ty   = t >> 4;
    const int q    = t >> 2;
    const int quad = t & 3;

    for (int i = t; i < 64 * 32; i += 128) {
        int p = i & 31, c = i >> 5;
        f0_s[c][p] = f0[(b * 64 + c) * 4096 + p0 + p];
    }
    if (t < 32) { m_s[t] = -1e30f; l_s[t] = 0.f; sx_s[t] = 0.f; sy_s[t] = 0.f; }
    __syncthreads();

    for (int j0 = 0; j0 < 4096; j0 += 128) {
        for (int i = t; i < 64 * 128; i += 128) {
            int j = i & 127, c = i >> 7;
            f1_sc[c * 128 + j] = f1[(b * 64 + c) * 4096 + j0 + j];
        }
        __syncthreads();

        u64 acc2[4][4];
        #pragma unroll
        for (int i = 0; i < 4; i++)
            #pragma unroll
            for (int jp = 0; jp < 4; jp++) acc2[i][jp] = 0ull;

        #pragma unroll 16
        for (int c = 0; c < 64; c++) {
            float4 a0 = *(const float4*)&f0_s[c][ty * 4];
            u64 ap[4] = { pack2(a0.x, a0.x), pack2(a0.y, a0.y),
                          pack2(a0.z, a0.z), pack2(a0.w, a0.w) };
            const u64* bp = (const u64*)&f1_sc[c * 128 + tx * 8];
            u64 b0 = bp[0], b1 = bp[1], b2 = bp[2], b3 = bp[3];
            #pragma unroll
            for (int i = 0; i < 4; i++) {
                acc2[i][0] = fma2(ap[i], b0, acc2[i][0]);
                acc2[i][1] = fma2(ap[i], b1, acc2[i][1]);
                acc2[i][2] = fma2(ap[i], b2, acc2[i][2]);
                acc2[i][3] = fma2(ap[i], b3, acc2[i][3]);
            }
        }
        __syncthreads();

        #pragma unroll
        for (int i = 0; i < 4; i++)
            #pragma unroll
            for (int jp = 0; jp < 4; jp++) {
                float lo, hi; unpack2(acc2[i][jp], lo, hi);
                f1_sc[(ty * 4 + i) * 132 + tx * 8 + 2 * jp]     = lo * 0.125f;
                f1_sc[(ty * 4 + i) * 132 + tx * 8 + 2 * jp + 1] = hi * 0.125f;
            }
        __syncthreads();

        float m_old = m_s[q];
        float sc[32];
        float tm = -1e30f;
        #pragma unroll
        for (int i = 0; i < 32; i++) {
            sc[i] = f1_sc[q * 132 + quad + 4 * i];
            tm = fmaxf(tm, sc[i]);
        }
        tm = fmaxf(tm, __shfl_xor_sync(0xffffffffu, tm, 1));
        tm = fmaxf(tm, __shfl_xor_sync(0xffffffffu, tm, 2));
        float nm = fmaxf(m_old, tm);

        float le = 0.f, lx = 0.f, ly = 0.f;
        #pragma unroll
        for (int i = 0; i < 32; i++) {
            int j   = j0 + quad + 4 * i;
            float e = __expf(sc[i] - nm);
            float gx = (float)((j & 63) * 2 + 1) * (1.f / 64.f) - 1.f;
            float gy = (float)((j >> 6) * 2 + 1) * (1.f / 64.f) - 1.f;
            le += e;
            lx = fmaf(e, gx, lx);
            ly = fmaf(e, gy, ly);
        }
        le += __shfl_xor_sync(0xffffffffu, le, 1);
        le += __shfl_xor_sync(0xffffffffu, le, 2);
        lx += __shfl_xor_sync(0xffffffffu, lx, 1);
        lx += __shfl_xor_sync(0xffffffffu, lx, 2);
        ly += __shfl_xor_sync(0xffffffffu, ly, 1);
        ly += __shfl_xor_sync(0xffffffffu, ly, 2);

        if (quad == 0) {
            float s = __expf(m_old - nm);
            l_s[q]  = l_s[q]  * s + le;
            sx_s[q] = sx_s[q] * s + lx;
            sy_s[q] = sy_s[q] * s + ly;
            m_s[q]  = nm;
        }
        __syncthreads();
    }

    if (t < 32) {
        float inv = 1.f / l_s[t];
        warp[(b * 2 + 0) * 4096 + p0 + t] = sx_s[t] * inv;
        warp[(b * 2 + 1) * 4096 + p0 + t] = sy_s[t] * inv;
    }
}

// ===========================================================================
// Winograd F(2x2, 3x3) pipeline
// ===========================================================================

// --- weight transform: U[xi][ci][co] = (G g G^T), zero for ci >= Cin -------
__global__ void wino_wtrans(const float* __restrict__ w, float* __restrict__ U,
                            int Cin, int K, int Co)
{
    int idx = blockIdx.x * blockDim.x + threadIdx.x;
    if (idx >= Co * K) return;
    int co = idx % Co;
    int ci = idx / Co;

    float g[3][3];
    if (ci < Cin) {
        #pragma unroll
        for (int i = 0; i < 3; i++)
            #pragma unroll
            for (int j = 0; j < 3; j++)
                g[i][j] = w[(co * Cin + ci) * 9 + i * 3 + j];
    } else {
        #pragma unroll
        for (int i = 0; i < 3; i++)
            #pragma unroll
            for (int j = 0; j < 3; j++) g[i][j] = 0.f;
    }

    float u[4][3];
    #pragma unroll
    for (int j = 0; j < 3; j++) {
        u[0][j] = g[0][j];
        u[1][j] = 0.5f * (g[0][j] + g[1][j] + g[2][j]);
        u[2][j] = 0.5f * (g[0][j] - g[1][j] + g[2][j]);
        u[3][j] = g[2][j];
    }
    #pragma unroll
    for (int i = 0; i < 4; i++) {
        float U0 = u[i][0];
        float U1 = 0.5f * (u[i][0] + u[i][1] + u[i][2]);
        float U2 = 0.5f * (u[i][0] - u[i][1] + u[i][2]);
        float U3 = u[i][2];
        U[((i * 4 + 0) * K + ci) * Co + co] = U0;
        U[((i * 4 + 1) * K + ci) * Co + co] = U1;
        U[((i * 4 + 2) * K + ci) * Co + co] = U2;
        U[((i * 4 + 3) * K + ci) * Co + co] = U3;
    }
}

// --- input transform: V[xi][ci][n] = B^T d B, with zero pad + BN fold ------
__global__ void wino_intrans(const float* __restrict__ in, const float* __restrict__ bn,
                             float* __restrict__ V,
                             int Cin, int K, int H, int W, int tilesW, int T)
{
    int idx = blockIdx.x * blockDim.x + threadIdx.x;
    if (idx >= K * T) return;
    int n  = idx % T;
    int ci = idx / T;

    int tilesH = H >> 1;
    int tpb = tilesW * tilesH;
    int b  = n / tpb;
    int r  = n - b * tpb;
    int th = r / tilesW;
    int tw = r - th * tilesW;

    float d[4][4];
    if (ci < Cin) {
        const float* ip = in + ((size_t)b * Cin + ci) * H * W;
        bool hasBN = (bn != nullptr);
        float mu = 0.f, rs = 0.f;
        if (hasBN) { mu = bn[ci]; rs = bn[Cin + ci]; }
        int h0 = th * 2 - 1, w0 = tw * 2 - 1;
        #pragma unroll
        for (int i = 0; i < 4; i++) {
            int h = h0 + i;
            #pragma unroll
            for (int j = 0; j < 4; j++) {
                int w = w0 + j;
                float v = 0.f;
                if ((unsigned)h < (unsigned)H && (unsigned)w < (unsigned)W) {
                    v = ip[h * W + w];
                    if (hasBN) v = fmaxf((v - mu) * rs, 0.f);
                }
                d[i][j] = v;
            }
        }
    } else {
        #pragma unroll
        for (int i = 0; i < 4; i++)
            #pragma unroll
            for (int j = 0; j < 4; j++) d[i][j] = 0.f;
    }

    float t0[4], t1[4], t2[4], t3[4];
    #pragma unroll
    for (int j = 0; j < 4; j++) {
        t0[j] = d[0][j] - d[2][j];
        t1[j] = d[1][j] + d[2][j];
        t2[j] = d[2][j] - d[1][j];
        t3[j] = d[1][j] - d[3][j];
    }
    float* Vp = V + (size_t)ci * T + n;
    size_t ps = (size_t)K * T;
    float* rows[4] = {t0, t1, t2, t3};
    #pragma unroll
    for (int i = 0; i < 4; i++) {
        float* ti = rows[i];
        Vp[(i * 4 + 0) * ps] = ti[0] - ti[2];
        Vp[(i * 4 + 1) * ps] = ti[1] + ti[2];
        Vp[(i * 4 + 2) * ps] = ti[2] - ti[1];
        Vp[(i * 4 + 3) * ps] = ti[1] - ti[3];
    }
}

// --- 16 batched GEMMs: M[xi][co][n] = sum_ci U[xi][ci][co] * V[xi][ci][n] --
// block: 256 thr, tile 64co x 128n, K-chunk 16. thread: 8co x 4n.
__global__ __launch_bounds__(256) void wino_gemm(
    const float* __restrict__ U, const float* __restrict__ V,
    float* __restrict__ M, int K, int Co, int T)
{
    const int xi = blockIdx.z;
    const int nb = blockIdx.x * 128;
    const int cb = blockIdx.y * 64;
    const float* Up = U + (size_t)xi * K * Co;
    const float* Vp = V + (size_t)xi * K * T;
    float*       Mp = M + (size_t)xi * Co * T;

    __shared__ __align__(16) float Us[16][64];
    __shared__ __align__(16) float Vs[16][128];

    const int t  = threadIdx.x;
    const int tn = (t & 31) * 4;
    const int tc = (t >> 5) * 8;

    float acc[8][4];
    #pragma unroll
    for (int i = 0; i < 8; i++)
        #pragma unroll
        for (int j = 0; j < 4; j++) acc[i][j] = 0.f;

    for (int k0 = 0; k0 < K; k0 += 16) {
        {
            int i = t * 4;
            int kk = i >> 6, cc = i & 63;
            *(float4*)&Us[kk][cc] = *(const float4*)&Up[(size_t)(k0 + kk) * Co + cb + cc];
        }
        {
            int i = t * 8;
            int kk = i >> 7, nn = i & 127;
            const float* src = &Vp[(size_t)(k0 + kk) * T + nb + nn];
            *(float4*)&Vs[kk][nn]     = *(const float4*)src;
            *(float4*)&Vs[kk][nn + 4] = *(const float4*)(src + 4);
        }
        __syncthreads();

        #pragma unroll
        for (int k = 0; k < 16; k++) {
            float a[8], bl[4];
            *(float4*)&a[0] = *(const float4*)&Us[k][tc];
            *(float4*)&a[4] = *(const float4*)&Us[k][tc + 4];
            *(float4*)&bl[0] = *(const float4*)&Vs[k][tn];
            #pragma unroll
            for (int i = 0; i < 8; i++)
                #pragma unroll
                for (int j = 0; j < 4; j++)
                    acc[i][j] = fmaf(a[i], bl[j], acc[i][j]);
        }
        __syncthreads();
    }

    #pragma unroll
    for (int i = 0; i < 8; i++)
        *(float4*)&Mp[(size_t)(cb + tc + i) * T + nb + tn] =
            make_float4(acc[i][0], acc[i][1], acc[i][2], acc[i][3]);
}

// --- output transform: Y = A^T M A, write NCHW -----------------------------
__global__ void wino_outtrans(const float* __restrict__ M, float* __restrict__ out,
                              int Co, int H, int W, int tilesW, int T)
{
    int idx = blockIdx.x * blockDim.x + threadIdx.x;
    if (idx >= Co * T) return;
    int n  = idx % T;
    int co = idx / T;

    int tilesH = H >> 1;
    int tpb = tilesW * tilesH;
    int b  = n / tpb;
    int r  = n - b * tpb;
    int th = r / tilesW;
    int tw = r - th * tilesW;

    float m[4][4];
    const float* Mp = M + (size_t)co * T + n;
    size_t ps = (size_t)Co * T;
    #pragma unroll
    for (int i = 0; i < 4; i++)
        #pragma unroll
        for (int j = 0; j < 4; j++)
            m[i][j] = Mp[(i * 4 + j) * ps];

    float s0[4], s1[4];
    #pragma unroll
    for (int j = 0; j < 4; j++) {
        s0[j] = m[0][j] + m[1][j] + m[2][j];
        s1[j] = m[1][j] - m[2][j] - m[3][j];
    }
    float y00 = s0[0] + s0[1] + s0[2];
    float y01 = s0[1] - s0[2] - s0[3];
    float y10 = s1[0] + s1[1] + s1[2];
    float y11 = s1[1] - s1[2] - s1[3];

    float* op = out + (((size_t)b * Co + co) * H + th * 2) * W + tw * 2;
    op[0]     = y00;
    op[1]     = y01;
    op[W]     = y10;
    op[W + 1] = y11;
}

// ---------------------------------------------------------------------------
// BN stats / bnrelu / gridsample / copies / upsample / 1x1 head
// ---------------------------------------------------------------------------
__global__ __launch_bounds__(512) void bnstats_kernel(
    const float* __restrict__ x, float* __restrict__ stats,
    int B_, int C, int HW)
{
    const int c = blockIdx.x;
    const int N = B_ * HW;
    float s = 0.f, sq = 0.f;
    for (int i = threadIdx.x; i < N; i += 512) {
        int b = i / HW, p = i - b * HW;
        float v = x[(b * C + c) * HW + p];
        s += v; sq = fmaf(v, v, sq);
    }
    __shared__ float rs[512], rq[512];
    rs[threadIdx.x] = s; rq[threadIdx.x] = sq;
    __syncthreads();
    for (int off = 256; off > 0; off >>= 1) {
        if (threadIdx.x < off) {
            rs[threadIdx.x] += rs[threadIdx.x + off];
            rq[threadIdx.x] += rq[threadIdx.x + off];
        }
        __syncthreads();
    }
    if (threadIdx.x == 0) {
        float m   = rs[0] / (float)N;
        float var = rq[0] / (float)N - m * m;
        stats[c]     = m;
        stats[C + c] = rsqrtf(var + 1e-5f);
    }
}

__global__ void bnrelu_kernel(float* __restrict__ x, const float* __restrict__ stats,
                              int C, int HW, int total)
{
    int i = blockIdx.x * blockDim.x + threadIdx.x;
    if (i >= total) return;
    int c = (i / HW) % C;
    float v = (x[i] - stats[c]) * stats[C + c];
    x[i] = v > 0.f ? v : 0.f;
}

__global__ void gridsample_kernel(
    const float* __restrict__ img, const float* __restrict__ coords,
    float* __restrict__ dst, int B_, int C, int H, int W,
    int cStrideB, int gyOff, int dstCtot, int dstCoff)
{
    int idx = blockIdx.x * blockDim.x + threadIdx.x;
    int HW = H * W;
    if (idx >= B_ * C * HW) return;
    int p = idx % HW;
    int c = (idx / HW) % C;
    int b = idx / (HW * C);

    float gx = coords[b * cStrideB + p];
    float gy = coords[b * cStrideB + gyOff + p];
    float x = (gx + 1.f) * (W * 0.5f) - 0.5f;
    float y = (gy + 1.f) * (H * 0.5f) - 0.5f;
    float x0f = floorf(x), y0f = floorf(y);
    float wx = x - x0f, wy = y - y0f;
    int x0 = (int)x0f, y0 = (int)y0f;

    const float* ip = img + (b * C + c) * HW;
    auto samp = [&](int yi, int xi) -> float {
        bool valid = (xi >= 0) && (xi < W) && (yi >= 0) && (yi < H);
        int yc = min(max(yi, 0), H - 1);
        int xc = min(max(xi, 0), W - 1);
        return valid ? ip[yc * W + xc] : 0.f;
    };
    float r = samp(y0,     x0    ) * (1.f - wx) * (1.f - wy)
            + samp(y0,     x0 + 1) * wx         * (1.f - wy)
            + samp(y0 + 1, x0    ) * (1.f - wx) * wy
            + samp(y0 + 1, x0 + 1) * wx         * wy;
    dst[((b * dstCtot) + dstCoff + c) * HW + p] = r;
}

__global__ void copy_strided_kernel(const float* __restrict__ src, float* __restrict__ dst,
                                    int perB, int srcStride, int dstStride, int B_)
{
    int i = blockIdx.x * blockDim.x + threadIdx.x;
    if (i >= B_ * perB) return;
    int b = i / perB, r = i - b * perB;
    dst[b * dstStride + r] = src[b * srcStride + r];
}

__global__ void upsample2x_kernel(const float* __restrict__ src, float* __restrict__ dst,
                                  int B_, int C, int Hi, int Wi)
{
    int Ho = Hi * 2, Wo = Wi * 2;
    int idx = blockIdx.x * blockDim.x + threadIdx.x;
    if (idx >= B_ * C * Ho * Wo) return;
    int wo = idx % Wo;
    int ho = (idx / Wo) % Ho;
    int bc = idx / (Wo * Ho);

    float sy = ho * 0.5f - 0.25f;
    float sx = wo * 0.5f - 0.25f;
    float fy = sy - floorf(sy);
    float fx = sx - floorf(sx);
    int y0 = (int)floorf(sy), x0 = (int)floorf(sx);
    int y0c = min(max(y0, 0), Hi - 1), y1c = min(max(y0 + 1, 0), Hi - 1);
    int x0c = min(max(x0, 0), Wi - 1), x1c = min(max(x0 + 1, 0), Wi - 1);

    const float* sp = src + bc * Hi * Wi;
    float v = sp[y0c * Wi + x0c] * (1.f - fy) * (1.f - fx)
            + sp[y0c * Wi + x1c] * (1.f - fy) * fx
            + sp[y1c * Wi + x0c] * fy * (1.f - fx)
            + sp[y1c * Wi + x1c] * fy * fx;
    dst[idx] = v;
}

__global__ void conv1x1_3_kernel(
    const float* __restrict__ x, const float* __restrict__ w5, const float* __restrict__ b5,
    const float* __restrict__ base, int baseC, int baseStrideB,
    float* __restrict__ out, int Cin, int HW, int B_)
{
    int idx = blockIdx.x * blockDim.x + threadIdx.x;
    if (idx >= B_ * HW) return;
    int b = idx / HW, p = idx - b * HW;

    float a0 = 0.f, a1 = 0.f, a2 = 0.f;
    const float* xp = x + (size_t)b * Cin * HW + p;
    for (int ci = 0; ci < Cin; ci++) {
        float v = xp[(size_t)ci * HW];
        a0 = fmaf(v, __ldg(&w5[ci]),            a0);
        a1 = fmaf(v, __ldg(&w5[Cin + ci]),      a1);
        a2 = fmaf(v, __ldg(&w5[2 * Cin + ci]),  a2);
    }
    float b0v = base[b * baseStrideB + p];
    float b1v = base[b * baseStrideB + HW + p];
    float b2v = (baseC > 2) ? base[b * baseStrideB + 2 * HW + p] : 0.f;

    out[(size_t)b * 3 * HW + p]           = a0 + __ldg(&b5[0]) + b0v;
    out[(size_t)b * 3 * HW + HW + p]      = a1 + __ldg(&b5[1]) + b1v;
    out[(size_t)b * 3 * HW + 2 * HW + p]  = a2 + __ldg(&b5[2]) + b2v;
}

// ---------------------------------------------------------------------------
// host-side helper to run one Winograd conv layer
// ---------------------------------------------------------------------------
static void wino_layer(const float* x, const float* wgt, const float* bn,
                       float* out, float* U, float* V, float* M,
                       int Cin, int Co, int H, int W)
{
    int K = (Cin + 15) & ~15;
    int tilesW = W >> 1, tilesH = H >> 1;
    int T = 4 * tilesW * tilesH;

    wino_wtrans<<<(Co * K + 255) / 256, 256>>>(wgt, U, Cin, K, Co);
    wino_intrans<<<(K * T + 255) / 256, 256>>>(x, bn, V, Cin, K, H, W, tilesW, T);
    dim3 gg(T / 128, Co / 64, 16);
    wino_gemm<<<gg, 256>>>(U, V, M, K, Co, T);
    wino_outtrans<<<(Co * T + 255) / 256, 256>>>(M, out, Co, H, W, tilesW, T);
}

// ---------------------------------------------------------------------------
extern "C" void kernel_launch(void* const* d_in, const int* in_sizes, int n_in,
                              void* d_out, int out_size)
{
    const float* f0c = (const float*)d_in[0];
    const float* f1c = (const float*)d_in[1];
    const float* f0f = (const float*)d_in[2];
    const float* f1f = (const float*)d_in[3];
    const float* cw1 = (const float*)d_in[4];
    const float* cw2 = (const float*)d_in[5];
    const float* cw3 = (const float*)d_in[6];
    const float* cw4 = (const float*)d_in[7];
    const float* cw5 = (const float*)d_in[8];
    const float* cb5 = (const float*)d_in[9];
    const float* fw1 = (const float*)d_in[10];
    const float* fw2 = (const float*)d_in[11];
    const float* fw3 = (const float*)d_in[12];
    const float* fw4 = (const float*)d_in[13];
    const float* fw5 = (const float*)d_in[14];
    const float* fb5 = (const float*)d_in[15];

    float *A, *Bb, *V, *M, *U, *warp, *stats;
    cudaGetSymbolAddress((void**)&A,     g_bufA);
    cudaGetSymbolAddress((void**)&Bb,    g_bufB);
    cudaGetSymbolAddress((void**)&V,     g_V);
    cudaGetSymbolAddress((void**)&M,     g_M);
    cudaGetSymbolAddress((void**)&U,     g_U);
    cudaGetSymbolAddress((void**)&warp,  g_warp);
    cudaGetSymbolAddress((void**)&stats, g_stats);

    float* outC = (float*)d_out;                 // (4,3,64,64)
    float* outF = outC + 4 * 3 * 64 * 64;        // (4,3,128,128)

    const int HWc = 64 * 64, HWf = 128 * 128;

    // ---- coarse stage ----
    corr_kernel<<<512, 128>>>(f0c, f1c, warp);

    copy_strided_kernel<<<(4 * 64 * HWc + 255) / 256, 256>>>(
        f0c, A, 64 * HWc, 64 * HWc, 130 * HWc, 4);
    copy_strided_kernel<<<(4 * 2 * HWc + 255) / 256, 256>>>(
        warp, A + 128 * HWc, 2 * HWc, 2 * HWc, 130 * HWc, 4);
    gridsample_kernel<<<(4 * 64 * HWc + 255) / 256, 256>>>(
        f1c, warp, A, 4, 64, 64, 64, 2 * HWc, HWc, 130, 64);

    wino_layer(A,  cw1, nullptr, Bb, U, V, M, 130, 256, 64, 64);
    bnstats_kernel<<<256, 512>>>(Bb, stats, 4, 256, HWc);

    wino_layer(Bb, cw2, stats,   A,  U, V, M, 256, 256, 64, 64);
    bnstats_kernel<<<256, 512>>>(A, stats, 4, 256, HWc);

    wino_layer(A,  cw3, stats,   Bb, U, V, M, 256, 256, 64, 64);
    bnstats_kernel<<<256, 512>>>(Bb, stats, 4, 256, HWc);

    wino_layer(Bb, cw4, stats,   A,  U, V, M, 256, 256, 64, 64);
    bnstats_kernel<<<256, 512>>>(A, stats, 4, 256, HWc);
    bnrelu_kernel<<<(4 * 256 * HWc + 255) / 256, 256>>>(A, stats, 256, HWc, 4 * 256 * HWc);

    conv1x1_3_kernel<<<(4 * HWc + 127) / 128, 128>>>(
        A, cw5, cb5, warp, 2, 2 * HWc, outC, 256, HWc, 4);

    // ---- fine stage ----
    upsample2x_kernel<<<(4 * 3 * HWf + 255) / 256, 256>>>(outC, outF, 4, 3, 64, 64);

    copy_strided_kernel<<<(4 * 24 * HWf + 255) / 256, 256>>>(
        f0f, Bb, 24 * HWf, 24 * HWf, 50 * HWf, 4);
    copy_strided_kernel<<<(4 * 2 * HWf + 255) / 256, 256>>>(
        outF, Bb + 48 * HWf, 2 * HWf, 3 * HWf, 50 * HWf, 4);
    gridsample_kernel<<<(4 * 24 * HWf + 255) / 256, 256>>>(
        f1f, outF, Bb, 4, 24, 128, 128, 3 * HWf, HWf, 50, 24);

    wino_layer(Bb, fw1, nullptr, A,  U, V, M, 50, 64, 128, 128);
    bnstats_kernel<<<64, 512>>>(A, stats, 4, 64, HWf);

    wino_layer(A,  fw2, stats,   Bb, U, V, M, 64, 64, 128, 128);
    bnstats_kernel<<<64, 512>>>(Bb, stats, 4, 64, HWf);

    wino_layer(Bb, fw3, stats,   A,  U, V, M, 64, 64, 128, 128);
    bnstats_kernel<<<64, 512>>>(A, stats, 4, 64, HWf);

    wino_layer(A,  fw4, stats,   Bb, U, V, M, 64, 64, 128, 128);
    bnstats_kernel<<<64, 512>>>(Bb, stats, 4, 64, HWf);
    bnrelu_kernel<<<(4 * 64 * HWf + 255) / 256, 256>>>(Bb, stats, 64, HWf, 4 * 64 * HWf);

    conv1x1_3_kernel<<<(4 * HWf + 127) / 128, 128>>>(
        Bb, fw5, fb5, outF, 3, 3 * HWf, outF, 64, HWf, 4);
}

// round 10
// speedup vs baseline: 3.3952x; 2.0803x over previous
#include <cuda_runtime.h>
#include <cuda_bf16.h>
#include <math.h>

typedef unsigned long long u64;

__device__ __forceinline__ u64 pack2(float lo, float hi) {
    u64 r; asm("mov.b64 %0,{%1,%2};" : "=l"(r) : "f"(lo), "f"(hi)); return r;
}
__device__ __forceinline__ void unpack2(u64 v, float& lo, float& hi) {
    asm("mov.b64 {%0,%1},%2;" : "=f"(lo), "=f"(hi) : "l"(v));
}
__device__ __forceinline__ u64 fma2(u64 a, u64 b, u64 c) {
    u64 d; asm("fma.rn.f32x2 %0,%1,%2,%3;" : "=l"(d) : "l"(a), "l"(b), "l"(c)); return d;
}

// ---------------- scratch (device globals; no allocations) ----------------
__device__ float g_bufA[4u * 256u * 64u * 64u];     // 16.8 MB
__device__ float g_bufB[4u * 256u * 64u * 64u];     // 16.8 MB
__device__ float g_V[16u * 256u * 4096u];           // 67 MB (Winograd V)
__device__ float g_M[16u * 256u * 4096u];           // 67 MB (Winograd M)
__device__ float g_U[36u * 256u * 256u];            // 9.4 MB (Winograd U)
__device__ float g_warp[4 * 2 * 64 * 64];
__device__ float g_stats[1024];                     // [mean(C) | rstd(C)]

// ---------------------------------------------------------------------------
// Kernel 1: fused correlation + softmax + expected grid position
// ---------------------------------------------------------------------------
__global__ __launch_bounds__(128) void corr_kernel(
    const float* __restrict__ f0, const float* __restrict__ f1,
    float* __restrict__ warp)
{
    const int b  = blockIdx.x >> 7;
    const int p0 = (blockIdx.x & 127) * 32;

    __shared__ __align__(16) float f0_s[64][32];
    __shared__ __align__(16) float f1_sc[64 * 128];
    __shared__ float m_s[32], l_s[32], sx_s[32], sy_s[32];

    const int t    = threadIdx.x;
    const int tx   = t & 15;
    const int ty   = t >> 4;
    const int q    = t >> 2;
    const int quad = t & 3;

    for (int i = t; i < 64 * 32; i += 128) {
        int p = i & 31, c = i >> 5;
        f0_s[c][p] = f0[(b * 64 + c) * 4096 + p0 + p];
    }
    if (t < 32) { m_s[t] = -1e30f; l_s[t] = 0.f; sx_s[t] = 0.f; sy_s[t] = 0.f; }
    __syncthreads();

    for (int j0 = 0; j0 < 4096; j0 += 128) {
        for (int i = t; i < 64 * 128; i += 128) {
            int j = i & 127, c = i >> 7;
            f1_sc[c * 128 + j] = f1[(b * 64 + c) * 4096 + j0 + j];
        }
        __syncthreads();

        u64 acc2[4][4];
        #pragma unroll
        for (int i = 0; i < 4; i++)
            #pragma unroll
            for (int jp = 0; jp < 4; jp++) acc2[i][jp] = 0ull;

        #pragma unroll 16
        for (int c = 0; c < 64; c++) {
            float4 a0 = *(const float4*)&f0_s[c][ty * 4];
            u64 ap[4] = { pack2(a0.x, a0.x), pack2(a0.y, a0.y),
                          pack2(a0.z, a0.z), pack2(a0.w, a0.w) };
            const u64* bp = (const u64*)&f1_sc[c * 128 + tx * 8];
            u64 b0 = bp[0], b1 = bp[1], b2 = bp[2], b3 = bp[3];
            #pragma unroll
            for (int i = 0; i < 4; i++) {
                acc2[i][0] = fma2(ap[i], b0, acc2[i][0]);
                acc2[i][1] = fma2(ap[i], b1, acc2[i][1]);
                acc2[i][2] = fma2(ap[i], b2, acc2[i][2]);
                acc2[i][3] = fma2(ap[i], b3, acc2[i][3]);
            }
        }
        __syncthreads();

        #pragma unroll
        for (int i = 0; i < 4; i++)
            #pragma unroll
            for (int jp = 0; jp < 4; jp++) {
                float lo, hi; unpack2(acc2[i][jp], lo, hi);
                f1_sc[(ty * 4 + i) * 132 + tx * 8 + 2 * jp]     = lo * 0.125f;
                f1_sc[(ty * 4 + i) * 132 + tx * 8 + 2 * jp + 1] = hi * 0.125f;
            }
        __syncthreads();

        float m_old = m_s[q];
        float sc[32];
        float tm = -1e30f;
        #pragma unroll
        for (int i = 0; i < 32; i++) {
            sc[i] = f1_sc[q * 132 + quad + 4 * i];
            tm = fmaxf(tm, sc[i]);
        }
        tm = fmaxf(tm, __shfl_xor_sync(0xffffffffu, tm, 1));
        tm = fmaxf(tm, __shfl_xor_sync(0xffffffffu, tm, 2));
        float nm = fmaxf(m_old, tm);

        float le = 0.f, lx = 0.f, ly = 0.f;
        #pragma unroll
        for (int i = 0; i < 32; i++) {
            int j   = j0 + quad + 4 * i;
            float e = __expf(sc[i] - nm);
            float gx = (float)((j & 63) * 2 + 1) * (1.f / 64.f) - 1.f;
            float gy = (float)((j >> 6) * 2 + 1) * (1.f / 64.f) - 1.f;
            le += e;
            lx = fmaf(e, gx, lx);
            ly = fmaf(e, gy, ly);
        }
        le += __shfl_xor_sync(0xffffffffu, le, 1);
        le += __shfl_xor_sync(0xffffffffu, le, 2);
        lx += __shfl_xor_sync(0xffffffffu, lx, 1);
        lx += __shfl_xor_sync(0xffffffffu, lx, 2);
        ly += __shfl_xor_sync(0xffffffffu, ly, 1);
        ly += __shfl_xor_sync(0xffffffffu, ly, 2);

        if (quad == 0) {
            float s = __expf(m_old - nm);
            l_s[q]  = l_s[q]  * s + le;
            sx_s[q] = sx_s[q] * s + lx;
            sy_s[q] = sy_s[q] * s + ly;
            m_s[q]  = nm;
        }
        __syncthreads();
    }

    if (t < 32) {
        float inv = 1.f / l_s[t];
        warp[(b * 2 + 0) * 4096 + p0 + t] = sx_s[t] * inv;
        warp[(b * 2 + 1) * 4096 + p0 + t] = sy_s[t] * inv;
    }
}

// ===========================================================================
// Winograd F(4x4, 3x3) pipeline (36-point transform, 4x MAC reduction)
// ===========================================================================

// G rows applied to a 3-vector
__device__ __forceinline__ void gmul(float a0, float a1, float a2, float o[6]) {
    o[0] = 0.25f * a0;
    o[1] = (-1.f / 6.f) * (a0 + a1 + a2);
    o[2] = (1.f / 6.f) * (-a0 + a1 - a2);
    o[3] = (1.f / 24.f) * a0 + (1.f / 12.f) * a1 + (1.f / 6.f) * a2;
    o[4] = (1.f / 24.f) * a0 - (1.f / 12.f) * a1 + (1.f / 6.f) * a2;
    o[5] = a2;
}

// --- weight transform: U[xi][ci][co] = G g G^T, zero pad ci ---------------
__global__ void wino_wtrans(const float* __restrict__ w, float* __restrict__ U,
                            int Cin, int K, int Co)
{
    int idx = blockIdx.x * blockDim.x + threadIdx.x;
    if (idx >= Co * K) return;
    int co = idx % Co;
    int ci = idx / Co;

    float g[3][3];
    #pragma unroll
    for (int i = 0; i < 3; i++)
        #pragma unroll
        for (int j = 0; j < 3; j++)
            g[i][j] = (ci < Cin) ? w[(co * Cin + ci) * 9 + i * 3 + j] : 0.f;

    // columns first: u = G g  (6x3)
    float u[6][3];
    #pragma unroll
    for (int j = 0; j < 3; j++) {
        float col[6];
        gmul(g[0][j], g[1][j], g[2][j], col);
        #pragma unroll
        for (int i = 0; i < 6; i++) u[i][j] = col[i];
    }
    // rows: U = u G^T (6x6)
    #pragma unroll
    for (int i = 0; i < 6; i++) {
        float row[6];
        gmul(u[i][0], u[i][1], u[i][2], row);
        #pragma unroll
        for (int j = 0; j < 6; j++)
            U[((size_t)(i * 6 + j) * K + ci) * Co + co] = row[j];
    }
}

// B^T applied to a 6-vector
__device__ __forceinline__ void btmul(const float x[6], float y[6]) {
    y[0] =  4.f * x[0] - 5.f * x[2] + x[4];
    y[1] = -4.f * x[1] - 4.f * x[2] + x[3] + x[4];
    y[2] =  4.f * x[1] - 4.f * x[2] - x[3] + x[4];
    y[3] = -2.f * x[1] -       x[2] + 2.f * x[3] + x[4];
    y[4] =  2.f * x[1] -       x[2] - 2.f * x[3] + x[4];
    y[5] =  4.f * x[1] - 5.f * x[3] + x[5];
}

// --- input transform: V[xi][ci][n] = B^T d B, zero pad + BN fold ----------
__global__ void wino_intrans(const float* __restrict__ in, const float* __restrict__ bn,
                             float* __restrict__ V,
                             int Cin, int K, int H, int W, int tilesW, int T)
{
    int idx = blockIdx.x * blockDim.x + threadIdx.x;
    if (idx >= K * T) return;
    int n  = idx % T;
    int ci = idx / T;

    int tilesH = H >> 2;
    int tpb = tilesW * tilesH;
    int b  = n / tpb;
    int r  = n - b * tpb;
    int th = r / tilesW;
    int tw = r - th * tilesW;

    float d[6][6];
    if (ci < Cin) {
        const float* ip = in + ((size_t)b * Cin + ci) * H * W;
        bool hasBN = (bn != nullptr);
        float mu = 0.f, rs = 0.f;
        if (hasBN) { mu = bn[ci]; rs = bn[Cin + ci]; }
        int h0 = th * 4 - 1, w0 = tw * 4 - 1;
        #pragma unroll
        for (int i = 0; i < 6; i++) {
            int h = h0 + i;
            #pragma unroll
            for (int j = 0; j < 6; j++) {
                int w = w0 + j;
                float v = 0.f;
                if ((unsigned)h < (unsigned)H && (unsigned)w < (unsigned)W) {
                    v = ip[h * W + w];
                    if (hasBN) v = fmaxf((v - mu) * rs, 0.f);
                }
                d[i][j] = v;
            }
        }
    } else {
        #pragma unroll
        for (int i = 0; i < 6; i++)
            #pragma unroll
            for (int j = 0; j < 6; j++) d[i][j] = 0.f;
    }

    // columns: tt = B^T d
    float tt[6][6];
    #pragma unroll
    for (int j = 0; j < 6; j++) {
        float col[6] = { d[0][j], d[1][j], d[2][j], d[3][j], d[4][j], d[5][j] };
        float o[6];
        btmul(col, o);
        #pragma unroll
        for (int i = 0; i < 6; i++) tt[i][j] = o[i];
    }
    // rows: V = tt B
    float* Vp = V + (size_t)ci * T + n;
    size_t ps = (size_t)K * T;
    #pragma unroll
    for (int i = 0; i < 6; i++) {
        float o[6];
        btmul(tt[i], o);
        #pragma unroll
        for (int j = 0; j < 6; j++)
            Vp[(size_t)(i * 6 + j) * ps] = o[j];
    }
}

// --- 36 batched GEMMs: M[xi][co][n] = sum_ci U[xi][ci][co] * V[xi][ci][n] --
// block: 256 thr, tile 64co x 128n, K-chunk 16. thread: 8co x 4n.
__global__ __launch_bounds__(256) void wino_gemm(
    const float* __restrict__ U, const float* __restrict__ V,
    float* __restrict__ M, int K, int Co, int T)
{
    const int xi = blockIdx.z;
    const int nb = blockIdx.x * 128;
    const int cb = blockIdx.y * 64;
    const float* Up = U + (size_t)xi * K * Co;
    const float* Vp = V + (size_t)xi * K * T;
    float*       Mp = M + (size_t)xi * Co * T;

    __shared__ __align__(16) float Us[16][64];
    __shared__ __align__(16) float Vs[16][128];

    const int t  = threadIdx.x;
    const int tn = (t & 31) * 4;
    const int tc = (t >> 5) * 8;

    float acc[8][4];
    #pragma unroll
    for (int i = 0; i < 8; i++)
        #pragma unroll
        for (int j = 0; j < 4; j++) acc[i][j] = 0.f;

    for (int k0 = 0; k0 < K; k0 += 16) {
        {
            int i = t * 4;
            int kk = i >> 6, cc = i & 63;
            *(float4*)&Us[kk][cc] = *(const float4*)&Up[(size_t)(k0 + kk) * Co + cb + cc];
        }
        {
            int i = t * 8;
            int kk = i >> 7, nn = i & 127;
            const float* src = &Vp[(size_t)(k0 + kk) * T + nb + nn];
            *(float4*)&Vs[kk][nn]     = *(const float4*)src;
            *(float4*)&Vs[kk][nn + 4] = *(const float4*)(src + 4);
        }
        __syncthreads();

        #pragma unroll
        for (int k = 0; k < 16; k++) {
            float a[8], bl[4];
            *(float4*)&a[0] = *(const float4*)&Us[k][tc];
            *(float4*)&a[4] = *(const float4*)&Us[k][tc + 4];
            *(float4*)&bl[0] = *(const float4*)&Vs[k][tn];
            #pragma unroll
            for (int i = 0; i < 8; i++)
                #pragma unroll
                for (int j = 0; j < 4; j++)
                    acc[i][j] = fmaf(a[i], bl[j], acc[i][j]);
        }
        __syncthreads();
    }

    #pragma unroll
    for (int i = 0; i < 8; i++)
        *(float4*)&Mp[(size_t)(cb + tc + i) * T + nb + tn] =
            make_float4(acc[i][0], acc[i][1], acc[i][2], acc[i][3]);
}

// A^T applied to a 6-vector -> 4
__device__ __forceinline__ void atmul(const float m[6], float y[4]) {
    y[0] = m[0] + m[1] + m[2] + m[3] + m[4];
    y[1] = m[1] - m[2] + 2.f * m[3] - 2.f * m[4];
    y[2] = m[1] + m[2] + 4.f * m[3] + 4.f * m[4];
    y[3] = m[1] - m[2] + 8.f * m[3] - 8.f * m[4] + m[5];
}

// --- output transform: Y = A^T M A, write NCHW 4x4 -------------------------
__global__ void wino_outtrans(const float* __restrict__ M, float* __restrict__ out,
                              int Co, int H, int W, int tilesW, int T)
{
    int idx = blockIdx.x * blockDim.x + threadIdx.x;
    if (idx >= Co * T) return;
    int n  = idx % T;
    int co = idx / T;

    int tilesH = H >> 2;
    int tpb = tilesW * tilesH;
    int b  = n / tpb;
    int r  = n - b * tpb;
    int th = r / tilesW;
    int tw = r - th * tilesW;

    float m[6][6];
    const float* Mp = M + (size_t)co * T + n;
    size_t ps = (size_t)Co * T;
    #pragma unroll
    for (int i = 0; i < 6; i++)
        #pragma unroll
        for (int j = 0; j < 6; j++)
            m[i][j] = Mp[(size_t)(i * 6 + j) * ps];

    // columns: s = A^T m  (4x6)
    float s[4][6];
    #pragma unroll
    for (int j = 0; j < 6; j++) {
        float col[6] = { m[0][j], m[1][j], m[2][j], m[3][j], m[4][j], m[5][j] };
        float o[4];
        atmul(col, o);
        #pragma unroll
        for (int i = 0; i < 4; i++) s[i][j] = o[i];
    }
    // rows: y = s A  (4x4)
    float* op = out + (((size_t)b * Co + co) * H + th * 4) * W + tw * 4;
    #pragma unroll
    for (int i = 0; i < 4; i++) {
        float o[4];
        atmul(s[i], o);
        op[i * W + 0] = o[0];
        op[i * W + 1] = o[1];
        op[i * W + 2] = o[2];
        op[i * W + 3] = o[3];
    }
}

// ---------------------------------------------------------------------------
// BN stats / gridsample / copies / upsample / 1x1 head (with BN fold)
// ---------------------------------------------------------------------------
__global__ __launch_bounds__(512) void bnstats_kernel(
    const float* __restrict__ x, float* __restrict__ stats,
    int B_, int C, int HW)
{
    const int c = blockIdx.x;
    const int N = B_ * HW;
    float s = 0.f, sq = 0.f;
    for (int i = threadIdx.x; i < N; i += 512) {
        int b = i / HW, p = i - b * HW;
        float v = x[(b * C + c) * HW + p];
        s += v; sq = fmaf(v, v, sq);
    }
    __shared__ float rs[512], rq[512];
    rs[threadIdx.x] = s; rq[threadIdx.x] = sq;
    __syncthreads();
    for (int off = 256; off > 0; off >>= 1) {
        if (threadIdx.x < off) {
            rs[threadIdx.x] += rs[threadIdx.x + off];
            rq[threadIdx.x] += rq[threadIdx.x + off];
        }
        __syncthreads();
    }
    if (threadIdx.x == 0) {
        float m   = rs[0] / (float)N;
        float var = rq[0] / (float)N - m * m;
        stats[c]     = m;
        stats[C + c] = rsqrtf(var + 1e-5f);
    }
}

__global__ void gridsample_kernel(
    const float* __restrict__ img, const float* __restrict__ coords,
    float* __restrict__ dst, int B_, int C, int H, int W,
    int cStrideB, int gyOff, int dstCtot, int dstCoff)
{
    int idx = blockIdx.x * blockDim.x + threadIdx.x;
    int HW = H * W;
    if (idx >= B_ * C * HW) return;
    int p = idx % HW;
    int c = (idx / HW) % C;
    int b = idx / (HW * C);

    float gx = coords[b * cStrideB + p];
    float gy = coords[b * cStrideB + gyOff + p];
    float x = (gx + 1.f) * (W * 0.5f) - 0.5f;
    float y = (gy + 1.f) * (H * 0.5f) - 0.5f;
    float x0f = floorf(x), y0f = floorf(y);
    float wx = x - x0f, wy = y - y0f;
    int x0 = (int)x0f, y0 = (int)y0f;

    const float* ip = img + (b * C + c) * HW;
    auto samp = [&](int yi, int xi) -> float {
        bool valid = (xi >= 0) && (xi < W) && (yi >= 0) && (yi < H);
        int yc = min(max(yi, 0), H - 1);
        int xc = min(max(xi, 0), W - 1);
        return valid ? ip[yc * W + xc] : 0.f;
    };
    float r = samp(y0,     x0    ) * (1.f - wx) * (1.f - wy)
            + samp(y0,     x0 + 1) * wx         * (1.f - wy)
            + samp(y0 + 1, x0    ) * (1.f - wx) * wy
            + samp(y0 + 1, x0 + 1) * wx         * wy;
    dst[((b * dstCtot) + dstCoff + c) * HW + p] = r;
}

__global__ void copy_strided_kernel(const float* __restrict__ src, float* __restrict__ dst,
                                    int perB, int srcStride, int dstStride, int B_)
{
    int i = blockIdx.x * blockDim.x + threadIdx.x;
    if (i >= B_ * perB) return;
    int b = i / perB, r = i - b * perB;
    dst[b * dstStride + r] = src[b * srcStride + r];
}

__global__ void upsample2x_kernel(const float* __restrict__ src, float* __restrict__ dst,
                                  int B_, int C, int Hi, int Wi)
{
    int Ho = Hi * 2, Wo = Wi * 2;
    int idx = blockIdx.x * blockDim.x + threadIdx.x;
    if (idx >= B_ * C * Ho * Wo) return;
    int wo = idx % Wo;
    int ho = (idx / Wo) % Ho;
    int bc = idx / (Wo * Ho);

    float sy = ho * 0.5f - 0.25f;
    float sx = wo * 0.5f - 0.25f;
    float fy = sy - floorf(sy);
    float fx = sx - floorf(sx);
    int y0 = (int)floorf(sy), x0 = (int)floorf(sx);
    int y0c = min(max(y0, 0), Hi - 1), y1c = min(max(y0 + 1, 0), Hi - 1);
    int x0c = min(max(x0, 0), Wi - 1), x1c = min(max(x0 + 1, 0), Wi - 1);

    const float* sp = src + bc * Hi * Wi;
    float v = sp[y0c * Wi + x0c] * (1.f - fy) * (1.f - fx)
            + sp[y0c * Wi + x1c] * (1.f - fy) * fx
            + sp[y1c * Wi + x0c] * fy * (1.f - fx)
            + sp[y1c * Wi + x1c] * fy * fx;
    dst[idx] = v;
}

// 1x1 conv to 3 ch + bias + base add; optional BN+ReLU fold on x via stats
__global__ void conv1x1_3_kernel(
    const float* __restrict__ x, const float* __restrict__ stats,
    const float* __restrict__ w5, const float* __restrict__ b5,
    const float* __restrict__ base, int baseC, int baseStrideB,
    float* __restrict__ out, int Cin, int HW, int B_)
{
    int idx = blockIdx.x * blockDim.x + threadIdx.x;
    if (idx >= B_ * HW) return;
    int b = idx / HW, p = idx - b * HW;

    float a0 = 0.f, a1 = 0.f, a2 = 0.f;
    const float* xp = x + (size_t)b * Cin * HW + p;
    for (int ci = 0; ci < Cin; ci++) {
        float v = xp[(size_t)ci * HW];
        v = fmaxf((v - __ldg(&stats[ci])) * __ldg(&stats[Cin + ci]), 0.f);
        a0 = fmaf(v, __ldg(&w5[ci]),            a0);
        a1 = fmaf(v, __ldg(&w5[Cin + ci]),      a1);
        a2 = fmaf(v, __ldg(&w5[2 * Cin + ci]),  a2);
    }
    float b0v = base[b * baseStrideB + p];
    float b1v = base[b * baseStrideB + HW + p];
    float b2v = (baseC > 2) ? base[b * baseStrideB + 2 * HW + p] : 0.f;

    out[(size_t)b * 3 * HW + p]           = a0 + __ldg(&b5[0]) + b0v;
    out[(size_t)b * 3 * HW + HW + p]      = a1 + __ldg(&b5[1]) + b1v;
    out[(size_t)b * 3 * HW + 2 * HW + p]  = a2 + __ldg(&b5[2]) + b2v;
}

// ---------------------------------------------------------------------------
// host-side helper: one Winograd F(4,3) conv layer
// ---------------------------------------------------------------------------
static void wino_layer(const float* x, const float* wgt, const float* bn,
                       float* out, float* U, float* V, float* M,
                       int Cin, int Co, int H, int W)
{
    int K = (Cin + 15) & ~15;
    int tilesW = W >> 2, tilesH = H >> 2;
    int T = 4 * tilesW * tilesH;

    wino_wtrans<<<(Co * K + 255) / 256, 256>>>(wgt, U, Cin, K, Co);
    wino_intrans<<<(K * T + 255) / 256, 256>>>(x, bn, V, Cin, K, H, W, tilesW, T);
    dim3 gg(T / 128, Co / 64, 36);
    wino_gemm<<<gg, 256>>>(U, V, M, K, Co, T);
    wino_outtrans<<<(Co * T + 255) / 256, 256>>>(M, out, Co, H, W, tilesW, T);
}

// ---------------------------------------------------------------------------
extern "C" void kernel_launch(void* const* d_in, const int* in_sizes, int n_in,
                              void* d_out, int out_size)
{
    const float* f0c = (const float*)d_in[0];
    const float* f1c = (const float*)d_in[1];
    const float* f0f = (const float*)d_in[2];
    const float* f1f = (const float*)d_in[3];
    const float* cw1 = (const float*)d_in[4];
    const float* cw2 = (const float*)d_in[5];
    const float* cw3 = (const float*)d_in[6];
    const float* cw4 = (const float*)d_in[7];
    const float* cw5 = (const float*)d_in[8];
    const float* cb5 = (const float*)d_in[9];
    const float* fw1 = (const float*)d_in[10];
    const float* fw2 = (const float*)d_in[11];
    const float* fw3 = (const float*)d_in[12];
    const float* fw4 = (const float*)d_in[13];
    const float* fw5 = (const float*)d_in[14];
    const float* fb5 = (const float*)d_in[15];

    float *A, *Bb, *V, *M, *U, *warp, *stats;
    cudaGetSymbolAddress((void**)&A,     g_bufA);
    cudaGetSymbolAddress((void**)&Bb,    g_bufB);
    cudaGetSymbolAddress((void**)&V,     g_V);
    cudaGetSymbolAddress((void**)&M,     g_M);
    cudaGetSymbolAddress((void**)&U,     g_U);
    cudaGetSymbolAddress((void**)&warp,  g_warp);
    cudaGetSymbolAddress((void**)&stats, g_stats);

    float* outC = (float*)d_out;                 // (4,3,64,64)
    float* outF = outC + 4 * 3 * 64 * 64;        // (4,3,128,128)

    const int HWc = 64 * 64, HWf = 128 * 128;

    // ---- coarse stage ----
    corr_kernel<<<512, 128>>>(f0c, f1c, warp);

    copy_strided_kernel<<<(4 * 64 * HWc + 255) / 256, 256>>>(
        f0c, A, 64 * HWc, 64 * HWc, 130 * HWc, 4);
    copy_strided_kernel<<<(4 * 2 * HWc + 255) / 256, 256>>>(
        warp, A + 128 * HWc, 2 * HWc, 2 * HWc, 130 * HWc, 4);
    gridsample_kernel<<<(4 * 64 * HWc + 255) / 256, 256>>>(
        f1c, warp, A, 4, 64, 64, 64, 2 * HWc, HWc, 130, 64);

    wino_layer(A,  cw1, nullptr, Bb, U, V, M, 130, 256, 64, 64);
    bnstats_kernel<<<256, 512>>>(Bb, stats, 4, 256, HWc);

    wino_layer(Bb, cw2, stats,   A,  U, V, M, 256, 256, 64, 64);
    bnstats_kernel<<<256, 512>>>(A, stats, 4, 256, HWc);

    wino_layer(A,  cw3, stats,   Bb, U, V, M, 256, 256, 64, 64);
    bnstats_kernel<<<256, 512>>>(Bb, stats, 4, 256, HWc);

    wino_layer(Bb, cw4, stats,   A,  U, V, M, 256, 256, 64, 64);
    bnstats_kernel<<<256, 512>>>(A, stats, 4, 256, HWc);

    conv1x1_3_kernel<<<(4 * HWc + 127) / 128, 128>>>(
        A, stats, cw5, cb5, warp, 2, 2 * HWc, outC, 256, HWc, 4);

    // ---- fine stage ----
    upsample2x_kernel<<<(4 * 3 * HWf + 255) / 256, 256>>>(outC, outF, 4, 3, 64, 64);

    copy_strided_kernel<<<(4 * 24 * HWf + 255) / 256, 256>>>(
        f0f, Bb, 24 * HWf, 24 * HWf, 50 * HWf, 4);
    copy_strided_kernel<<<(4 * 2 * HWf + 255) / 256, 256>>>(
        outF, Bb + 48 * HWf, 2 * HWf, 3 * HWf, 50 * HWf, 4);
    gridsample_kernel<<<(4 * 24 * HWf + 255) / 256, 256>>>(
        f1f, outF, Bb, 4, 24, 128, 128, 3 * HWf, HWf, 50, 24);

    wino_layer(Bb, fw1, nullptr, A,  U, V, M, 50, 64, 128, 128);
    bnstats_kernel<<<64, 512>>>(A, stats, 4, 64, HWf);

    wino_layer(A,  fw2, stats,   Bb, U, V, M, 64, 64, 128, 128);
    bnstats_kernel<<<64, 512>>>(Bb, stats, 4, 64, HWf);

    wino_layer(Bb, fw3, stats,   A,  U, V, M, 64, 64, 128, 128);
    bnstats_kernel<<<64, 512>>>(A, stats, 4, 64, HWf);

    wino_layer(A,  fw4, stats,   Bb, U, V, M, 64, 64, 128, 128);
    bnstats_kernel<<<64, 512>>>(Bb, stats, 4, 64, HWf);

    conv1x1_3_kernel<<<(4 * HWf + 127) / 128, 128>>>(
        Bb, stats, fw5, fb5, outF, 3, 3 * HWf, outF, 64, HWf, 4);
}

// round 11
// speedup vs baseline: 3.6933x; 1.0878x over previous
#include <cuda_runtime.h>
#include <cuda_bf16.h>
#include <math.h>

typedef unsigned long long u64;

__device__ __forceinline__ u64 pack2(float lo, float hi) {
    u64 r; asm("mov.b64 %0,{%1,%2};" : "=l"(r) : "f"(lo), "f"(hi)); return r;
}
__device__ __forceinline__ void unpack2(u64 v, float& lo, float& hi) {
    asm("mov.b64 {%0,%1},%2;" : "=f"(lo), "=f"(hi) : "l"(v));
}
__device__ __forceinline__ u64 fma2(u64 a, u64 b, u64 c) {
    u64 d; asm("fma.rn.f32x2 %0,%1,%2,%3;" : "=l"(d) : "l"(a), "l"(b), "l"(c)); return d;
}

// ---------------- scratch (device globals; no allocations) ----------------
__device__ float g_bufA[4u * 256u * 64u * 64u];     // 16.8 MB
__device__ float g_bufB[4u * 256u * 64u * 64u];     // 16.8 MB
__device__ float g_V[16u * 256u * 4096u];           // 67 MB (Winograd V)
__device__ float g_M[16u * 256u * 4096u];           // 67 MB (Winograd M)
__device__ float g_U[9u * 1024u * 1024u];           // 36 MB (all layers' U)
__device__ float2 g_bnpart[8192];                   // per-warp BN partials
__device__ float g_warp[4 * 2 * 64 * 64];
__device__ float g_stats[1024];                     // [mean(C) | rstd(C)]

// U offsets per layer (floats)
#define UO1  0u
#define UO2  1327104u      // + 36*144*256
#define UO3  3686400u      // + 36*256*256
#define UO4  6045696u
#define UF1  8404992u
#define UF2  8552448u      // + 36*64*64
#define UF3  8699904u
#define UF4  8847360u

// ---------------------------------------------------------------------------
// Kernel 1: fused correlation + softmax + expected grid position
// ---------------------------------------------------------------------------
__global__ __launch_bounds__(128) void corr_kernel(
    const float* __restrict__ f0, const float* __restrict__ f1,
    float* __restrict__ warp)
{
    const int b  = blockIdx.x >> 7;
    const int p0 = (blockIdx.x & 127) * 32;

    __shared__ __align__(16) float f0_s[64][32];
    __shared__ __align__(16) float f1_sc[64 * 128];
    __shared__ float m_s[32], l_s[32], sx_s[32], sy_s[32];

    const int t    = threadIdx.x;
    const int tx   = t & 15;
    const int ty   = t >> 4;
    const int q    = t >> 2;
    const int quad = t & 3;

    for (int i = t; i < 64 * 32; i += 128) {
        int p = i & 31, c = i >> 5;
        f0_s[c][p] = f0[(b * 64 + c) * 4096 + p0 + p];
    }
    if (t < 32) { m_s[t] = -1e30f; l_s[t] = 0.f; sx_s[t] = 0.f; sy_s[t] = 0.f; }
    __syncthreads();

    for (int j0 = 0; j0 < 4096; j0 += 128) {
        for (int i = t; i < 64 * 128; i += 128) {
            int j = i & 127, c = i >> 7;
            f1_sc[c * 128 + j] = f1[(b * 64 + c) * 4096 + j0 + j];
        }
        __syncthreads();

        u64 acc2[4][4];
        #pragma unroll
        for (int i = 0; i < 4; i++)
            #pragma unroll
            for (int jp = 0; jp < 4; jp++) acc2[i][jp] = 0ull;

        #pragma unroll 16
        for (int c = 0; c < 64; c++) {
            float4 a0 = *(const float4*)&f0_s[c][ty * 4];
            u64 ap[4] = { pack2(a0.x, a0.x), pack2(a0.y, a0.y),
                          pack2(a0.z, a0.z), pack2(a0.w, a0.w) };
            const u64* bp = (const u64*)&f1_sc[c * 128 + tx * 8];
            u64 b0 = bp[0], b1 = bp[1], b2 = bp[2], b3 = bp[3];
            #pragma unroll
            for (int i = 0; i < 4; i++) {
                acc2[i][0] = fma2(ap[i], b0, acc2[i][0]);
                acc2[i][1] = fma2(ap[i], b1, acc2[i][1]);
                acc2[i][2] = fma2(ap[i], b2, acc2[i][2]);
                acc2[i][3] = fma2(ap[i], b3, acc2[i][3]);
            }
        }
        __syncthreads();

        #pragma unroll
        for (int i = 0; i < 4; i++)
            #pragma unroll
            for (int jp = 0; jp < 4; jp++) {
                float lo, hi; unpack2(acc2[i][jp], lo, hi);
                f1_sc[(ty * 4 + i) * 132 + tx * 8 + 2 * jp]     = lo * 0.125f;
                f1_sc[(ty * 4 + i) * 132 + tx * 8 + 2 * jp + 1] = hi * 0.125f;
            }
        __syncthreads();

        float m_old = m_s[q];
        float sc[32];
        float tm = -1e30f;
        #pragma unroll
        for (int i = 0; i < 32; i++) {
            sc[i] = f1_sc[q * 132 + quad + 4 * i];
            tm = fmaxf(tm, sc[i]);
        }
        tm = fmaxf(tm, __shfl_xor_sync(0xffffffffu, tm, 1));
        tm = fmaxf(tm, __shfl_xor_sync(0xffffffffu, tm, 2));
        float nm = fmaxf(m_old, tm);

        float le = 0.f, lx = 0.f, ly = 0.f;
        #pragma unroll
        for (int i = 0; i < 32; i++) {
            int j   = j0 + quad + 4 * i;
            float e = __expf(sc[i] - nm);
            float gx = (float)((j & 63) * 2 + 1) * (1.f / 64.f) - 1.f;
            float gy = (float)((j >> 6) * 2 + 1) * (1.f / 64.f) - 1.f;
            le += e;
            lx = fmaf(e, gx, lx);
            ly = fmaf(e, gy, ly);
        }
        le += __shfl_xor_sync(0xffffffffu, le, 1);
        le += __shfl_xor_sync(0xffffffffu, le, 2);
        lx += __shfl_xor_sync(0xffffffffu, lx, 1);
        lx += __shfl_xor_sync(0xffffffffu, lx, 2);
        ly += __shfl_xor_sync(0xffffffffu, ly, 1);
        ly += __shfl_xor_sync(0xffffffffu, ly, 2);

        if (quad == 0) {
            float s = __expf(m_old - nm);
            l_s[q]  = l_s[q]  * s + le;
            sx_s[q] = sx_s[q] * s + lx;
            sy_s[q] = sy_s[q] * s + ly;
            m_s[q]  = nm;
        }
        __syncthreads();
    }

    if (t < 32) {
        float inv = 1.f / l_s[t];
        warp[(b * 2 + 0) * 4096 + p0 + t] = sx_s[t] * inv;
        warp[(b * 2 + 1) * 4096 + p0 + t] = sy_s[t] * inv;
    }
}

// ===========================================================================
// Winograd F(4x4, 3x3)
// ===========================================================================

__device__ __forceinline__ void gmul(float a0, float a1, float a2, float o[6]) {
    o[0] = 0.25f * a0;
    o[1] = (-1.f / 6.f) * (a0 + a1 + a2);
    o[2] = (1.f / 6.f) * (-a0 + a1 - a2);
    o[3] = (1.f / 24.f) * a0 + (1.f / 12.f) * a1 + (1.f / 6.f) * a2;
    o[4] = (1.f / 24.f) * a0 - (1.f / 12.f) * a1 + (1.f / 6.f) * a2;
    o[5] = a2;
}

// --- one fused weight transform for ALL 8 layers ---------------------------
__global__ void wino_wtrans_all(
    const float* __restrict__ cw1, const float* __restrict__ cw2,
    const float* __restrict__ cw3, const float* __restrict__ cw4,
    const float* __restrict__ fw1, const float* __restrict__ fw2,
    const float* __restrict__ fw3, const float* __restrict__ fw4,
    float* __restrict__ U)
{
    int idx = blockIdx.x * blockDim.x + threadIdx.x;
    // segment select
    const float* w; int Cin, K, Co; unsigned base;
    if      (idx < 36864)  { w = cw1; Cin = 130; K = 144; Co = 256; base = UO1; }
    else if (idx < 102400) { w = cw2; Cin = 256; K = 256; Co = 256; base = UO2; idx -= 36864; }
    else if (idx < 167936) { w = cw3; Cin = 256; K = 256; Co = 256; base = UO3; idx -= 102400; }
    else if (idx < 233472) { w = cw4; Cin = 256; K = 256; Co = 256; base = UO4; idx -= 167936; }
    else if (idx < 237568) { w = fw1; Cin = 50;  K = 64;  Co = 64;  base = UF1; idx -= 233472; }
    else if (idx < 241664) { w = fw2; Cin = 64;  K = 64;  Co = 64;  base = UF2; idx -= 237568; }
    else if (idx < 245760) { w = fw3; Cin = 64;  K = 64;  Co = 64;  base = UF3; idx -= 241664; }
    else if (idx < 249856) { w = fw4; Cin = 64;  K = 64;  Co = 64;  base = UF4; idx -= 245760; }
    else return;

    int co = idx % Co;
    int ci = idx / Co;

    float g[3][3];
    #pragma unroll
    for (int i = 0; i < 3; i++)
        #pragma unroll
        for (int j = 0; j < 3; j++)
            g[i][j] = (ci < Cin) ? w[(co * Cin + ci) * 9 + i * 3 + j] : 0.f;

    float u[6][3];
    #pragma unroll
    for (int j = 0; j < 3; j++) {
        float col[6];
        gmul(g[0][j], g[1][j], g[2][j], col);
        #pragma unroll
        for (int i = 0; i < 6; i++) u[i][j] = col[i];
    }
    #pragma unroll
    for (int i = 0; i < 6; i++) {
        float row[6];
        gmul(u[i][0], u[i][1], u[i][2], row);
        #pragma unroll
        for (int j = 0; j < 6; j++)
            U[base + ((size_t)(i * 6 + j) * K + ci) * Co + co] = row[j];
    }
}

__device__ __forceinline__ void btmul(const float x[6], float y[6]) {
    y[0] =  4.f * x[0] - 5.f * x[2] + x[4];
    y[1] = -4.f * x[1] - 4.f * x[2] + x[3] + x[4];
    y[2] =  4.f * x[1] - 4.f * x[2] - x[3] + x[4];
    y[3] = -2.f * x[1] -       x[2] + 2.f * x[3] + x[4];
    y[4] =  2.f * x[1] -       x[2] - 2.f * x[3] + x[4];
    y[5] =  4.f * x[1] - 5.f * x[3] + x[5];
}

// --- input transform: V[xi][ci][n] = B^T d B, zero pad + BN fold ----------
__global__ void wino_intrans(const float* __restrict__ in, const float* __restrict__ bn,
                             float* __restrict__ V,
                             int Cin, int K, int H, int W, int tilesW, int T)
{
    int idx = blockIdx.x * blockDim.x + threadIdx.x;
    if (idx >= K * T) return;
    int n  = idx % T;
    int ci = idx / T;

    int tilesH = H >> 2;
    int tpb = tilesW * tilesH;
    int b  = n / tpb;
    int r  = n - b * tpb;
    int th = r / tilesW;
    int tw = r - th * tilesW;

    float d[6][6];
    if (ci < Cin) {
        const float* ip = in + ((size_t)b * Cin + ci) * H * W;
        bool hasBN = (bn != nullptr);
        float mu = 0.f, rs = 0.f;
        if (hasBN) { mu = bn[ci]; rs = bn[Cin + ci]; }
        int h0 = th * 4 - 1, w0 = tw * 4 - 1;
        #pragma unroll
        for (int i = 0; i < 6; i++) {
            int h = h0 + i;
            #pragma unroll
            for (int j = 0; j < 6; j++) {
                int w = w0 + j;
                float v = 0.f;
                if ((unsigned)h < (unsigned)H && (unsigned)w < (unsigned)W) {
                    v = ip[h * W + w];
                    if (hasBN) v = fmaxf((v - mu) * rs, 0.f);
                }
                d[i][j] = v;
            }
        }
    } else {
        #pragma unroll
        for (int i = 0; i < 6; i++)
            #pragma unroll
            for (int j = 0; j < 6; j++) d[i][j] = 0.f;
    }

    float tt[6][6];
    #pragma unroll
    for (int j = 0; j < 6; j++) {
        float col[6] = { d[0][j], d[1][j], d[2][j], d[3][j], d[4][j], d[5][j] };
        float o[6];
        btmul(col, o);
        #pragma unroll
        for (int i = 0; i < 6; i++) tt[i][j] = o[i];
    }
    float* Vp = V + (size_t)ci * T + n;
    size_t ps = (size_t)K * T;
    #pragma unroll
    for (int i = 0; i < 6; i++) {
        float o[6];
        btmul(tt[i], o);
        #pragma unroll
        for (int j = 0; j < 6; j++)
            Vp[(size_t)(i * 6 + j) * ps] = o[j];
    }
}

// --- 36 batched GEMMs, register double-buffered ----------------------------
__global__ __launch_bounds__(256) void wino_gemm(
    const float* __restrict__ U, const float* __restrict__ V,
    float* __restrict__ M, int K, int Co, int T)
{
    const int xi = blockIdx.z;
    const int nb = blockIdx.x * 128;
    const int cb = blockIdx.y * 64;
    const float* Up = U + (size_t)xi * K * Co;
    const float* Vp = V + (size_t)xi * K * T;
    float*       Mp = M + (size_t)xi * Co * T;

    __shared__ __align__(16) float Us[16][64];
    __shared__ __align__(16) float Vs[16][128];

    const int t  = threadIdx.x;
    const int tn = (t & 31) * 4;
    const int tc = (t >> 5) * 8;

    const int ukk = (t * 4) >> 6, ucc = (t * 4) & 63;
    const int vkk = (t * 8) >> 7, vnn = (t * 8) & 127;

    float acc[8][4];
    #pragma unroll
    for (int i = 0; i < 8; i++)
        #pragma unroll
        for (int j = 0; j < 4; j++) acc[i][j] = 0.f;

    float4 ru, rv0, rv1;
    ru  = *(const float4*)&Up[(size_t)ukk * Co + cb + ucc];
    rv0 = *(const float4*)&Vp[(size_t)vkk * T + nb + vnn];
    rv1 = *(const float4*)&Vp[(size_t)vkk * T + nb + vnn + 4];

    const int nChunks = K >> 4;
    for (int c = 0; c < nChunks; c++) {
        if (c > 0) __syncthreads();
        *(float4*)&Us[ukk][ucc]     = ru;
        *(float4*)&Vs[vkk][vnn]     = rv0;
        *(float4*)&Vs[vkk][vnn + 4] = rv1;
        __syncthreads();
        if (c + 1 < nChunks) {
            int k0 = (c + 1) * 16;
            ru  = *(const float4*)&Up[(size_t)(k0 + ukk) * Co + cb + ucc];
            rv0 = *(const float4*)&Vp[(size_t)(k0 + vkk) * T + nb + vnn];
            rv1 = *(const float4*)&Vp[(size_t)(k0 + vkk) * T + nb + vnn + 4];
        }

        #pragma unroll
        for (int k = 0; k < 16; k++) {
            float a[8], bl[4];
            *(float4*)&a[0] = *(const float4*)&Us[k][tc];
            *(float4*)&a[4] = *(const float4*)&Us[k][tc + 4];
            *(float4*)&bl[0] = *(const float4*)&Vs[k][tn];
            #pragma unroll
            for (int i = 0; i < 8; i++)
                #pragma unroll
                for (int j = 0; j < 4; j++)
                    acc[i][j] = fmaf(a[i], bl[j], acc[i][j]);
        }
    }

    #pragma unroll
    for (int i = 0; i < 8; i++)
        *(float4*)&Mp[(size_t)(cb + tc + i) * T + nb + tn] =
            make_float4(acc[i][0], acc[i][1], acc[i][2], acc[i][3]);
}

__device__ __forceinline__ void atmul(const float m[6], float y[4]) {
    y[0] = m[0] + m[1] + m[2] + m[3] + m[4];
    y[1] = m[1] - m[2] + 2.f * m[3] - 2.f * m[4];
    y[2] = m[1] + m[2] + 4.f * m[3] + 4.f * m[4];
    y[3] = m[1] - m[2] + 8.f * m[3] - 8.f * m[4] + m[5];
}

// --- output transform + fused BN partial sums ------------------------------
__global__ __launch_bounds__(256) void wino_outtrans(
    const float* __restrict__ M, float* __restrict__ out,
    float2* __restrict__ part, int Co, int H, int W, int tilesW, int T)
{
    int idx = blockIdx.x * 256 + threadIdx.x;
    int n  = idx % T;
    int co = idx / T;

    int tilesH = H >> 2;
    int tpb = tilesW * tilesH;
    int b  = n / tpb;
    int r  = n - b * tpb;
    int th = r / tilesW;
    int tw = r - th * tilesW;

    float m[6][6];
    const float* Mp = M + (size_t)co * T + n;
    size_t ps = (size_t)Co * T;
    #pragma unroll
    for (int i = 0; i < 6; i++)
        #pragma unroll
        for (int j = 0; j < 6; j++)
            m[i][j] = Mp[(size_t)(i * 6 + j) * ps];

    float s[4][6];
    #pragma unroll
    for (int j = 0; j < 6; j++) {
        float col[6] = { m[0][j], m[1][j], m[2][j], m[3][j], m[4][j], m[5][j] };
        float o[4];
        atmul(col, o);
        #pragma unroll
        for (int i = 0; i < 4; i++) s[i][j] = o[i];
    }

    float sum = 0.f, sq = 0.f;
    float* op = out + (((size_t)b * Co + co) * H + th * 4) * W + tw * 4;
    #pragma unroll
    for (int i = 0; i < 4; i++) {
        float o[4];
        atmul(s[i], o);
        op[i * W + 0] = o[0];
        op[i * W + 1] = o[1];
        op[i * W + 2] = o[2];
        op[i * W + 3] = o[3];
        #pragma unroll
        for (int j = 0; j < 4; j++) { sum += o[j]; sq = fmaf(o[j], o[j], sq); }
    }

    // warp reduce (warp covers 32 consecutive n of same co)
    #pragma unroll
    for (int off = 16; off > 0; off >>= 1) {
        sum += __shfl_xor_sync(0xffffffffu, sum, off);
        sq  += __shfl_xor_sync(0xffffffffu, sq,  off);
    }
    if ((threadIdx.x & 31) == 0)
        part[co * (T >> 5) + (n >> 5)] = make_float2(sum, sq);
}

// --- finalize BN stats from partials (deterministic) -----------------------
__global__ void bn_finalize(const float2* __restrict__ part, float* __restrict__ stats,
                            int C, int nparts, float invN)
{
    int c = threadIdx.x;
    if (c >= C) return;
    float s = 0.f, sq = 0.f;
    for (int j = 0; j < nparts; j++) {
        float2 v = part[c * nparts + j];
        s += v.x; sq += v.y;
    }
    float m   = s * invN;
    float var = sq * invN - m * m;
    stats[c]     = m;
    stats[C + c] = rsqrtf(var + 1e-5f);
}

// ---------------------------------------------------------------------------
// fused concat assembly (copy + gridsample + coords)
// ---------------------------------------------------------------------------
__device__ __forceinline__ float gs_sample(const float* __restrict__ ip,
                                           float gx, float gy, int H, int W)
{
    float x = (gx + 1.f) * (W * 0.5f) - 0.5f;
    float y = (gy + 1.f) * (H * 0.5f) - 0.5f;
    float x0f = floorf(x), y0f = floorf(y);
    float wx = x - x0f, wy = y - y0f;
    int x0 = (int)x0f, y0 = (int)y0f;
    auto samp = [&](int yi, int xi) -> float {
        bool valid = (xi >= 0) && (xi < W) && (yi >= 0) && (yi < H);
        int yc = min(max(yi, 0), H - 1);
        int xc = min(max(xi, 0), W - 1);
        return valid ? ip[yc * W + xc] : 0.f;
    };
    return samp(y0,     x0    ) * (1.f - wx) * (1.f - wy)
         + samp(y0,     x0 + 1) * wx         * (1.f - wy)
         + samp(y0 + 1, x0    ) * (1.f - wx) * wy
         + samp(y0 + 1, x0 + 1) * wx         * wy;
}

// coarse concat: dst 130ch = [f0c(64) | gridsample(f1c, warp)(64) | warp(2)]
__global__ void concat_coarse(const float* __restrict__ f0c, const float* __restrict__ f1c,
                              const float* __restrict__ warp, float* __restrict__ dst)
{
    const int HW = 4096;
    int idx = blockIdx.x * blockDim.x + threadIdx.x;
    if (idx >= 4 * 130 * HW) return;
    int p = idx % HW;
    int c = (idx / HW) % 130;
    int b = idx / (HW * 130);

    float v;
    if (c < 64) {
        v = f0c[((size_t)b * 64 + c) * HW + p];
    } else if (c < 128) {
        float gx = warp[(b * 2 + 0) * HW + p];
        float gy = warp[(b * 2 + 1) * HW + p];
        v = gs_sample(f1c + ((size_t)b * 64 + (c - 64)) * HW, gx, gy, 64, 64);
    } else {
        v = warp[(b * 2 + (c - 128)) * HW + p];
    }
    dst[((size_t)b * 130 + c) * HW + p] = v;
}

// fine concat: dst 50ch = [f0f(24) | gridsample(f1f, up)(24) | up[0:2](2)]
__global__ void concat_fine(const float* __restrict__ f0f, const float* __restrict__ f1f,
                            const float* __restrict__ up, float* __restrict__ dst)
{
    const int HW = 16384;
    int idx = blockIdx.x * blockDim.x + threadIdx.x;
    if (idx >= 4 * 50 * HW) return;
    int p = idx % HW;
    int c = (idx / HW) % 50;
    int b = idx / (HW * 50);

    float v;
    if (c < 24) {
        v = f0f[((size_t)b * 24 + c) * HW + p];
    } else if (c < 48) {
        float gx = up[((size_t)b * 3 + 0) * HW + p];
        float gy = up[((size_t)b * 3 + 1) * HW + p];
        v = gs_sample(f1f + ((size_t)b * 24 + (c - 24)) * HW, gx, gy, 128, 128);
    } else {
        v = up[((size_t)b * 3 + (c - 48)) * HW + p];
    }
    dst[((size_t)b * 50 + c) * HW + p] = v;
}

// ---------------------------------------------------------------------------
__global__ void upsample2x_kernel(const float* __restrict__ src, float* __restrict__ dst,
                                  int B_, int C, int Hi, int Wi)
{
    int Ho = Hi * 2, Wo = Wi * 2;
    int idx = blockIdx.x * blockDim.x + threadIdx.x;
    if (idx >= B_ * C * Ho * Wo) return;
    int wo = idx % Wo;
    int ho = (idx / Wo) % Ho;
    int bc = idx / (Wo * Ho);

    float sy = ho * 0.5f - 0.25f;
    float sx = wo * 0.5f - 0.25f;
    float fy = sy - floorf(sy);
    float fx = sx - floorf(sx);
    int y0 = (int)floorf(sy), x0 = (int)floorf(sx);
    int y0c = min(max(y0, 0), Hi - 1), y1c = min(max(y0 + 1, 0), Hi - 1);
    int x0c = min(max(x0, 0), Wi - 1), x1c = min(max(x0 + 1, 0), Wi - 1);

    const float* sp = src + bc * Hi * Wi;
    float v = sp[y0c * Wi + x0c] * (1.f - fy) * (1.f - fx)
            + sp[y0c * Wi + x1c] * (1.f - fy) * fx
            + sp[y1c * Wi + x0c] * fy * (1.f - fx)
            + sp[y1c * Wi + x1c] * fy * fx;
    dst[idx] = v;
}

// 1x1 conv to 3 ch + bias + base add, BN+ReLU fold on x via stats
__global__ void conv1x1_3_kernel(
    const float* __restrict__ x, const float* __restrict__ stats,
    const float* __restrict__ w5, const float* __restrict__ b5,
    const float* __restrict__ base, int baseC, int baseStrideB,
    float* __restrict__ out, int Cin, int HW, int B_)
{
    int idx = blockIdx.x * blockDim.x + threadIdx.x;
    if (idx >= B_ * HW) return;
    int b = idx / HW, p = idx - b * HW;

    float a0 = 0.f, a1 = 0.f, a2 = 0.f;
    const float* xp = x + (size_t)b * Cin * HW + p;
    for (int ci = 0; ci < Cin; ci++) {
        float v = xp[(size_t)ci * HW];
        v = fmaxf((v - __ldg(&stats[ci])) * __ldg(&stats[Cin + ci]), 0.f);
        a0 = fmaf(v, __ldg(&w5[ci]),            a0);
        a1 = fmaf(v, __ldg(&w5[Cin + ci]),      a1);
        a2 = fmaf(v, __ldg(&w5[2 * Cin + ci]),  a2);
    }
    float b0v = base[b * baseStrideB + p];
    float b1v = base[b * baseStrideB + HW + p];
    float b2v = (baseC > 2) ? base[b * baseStrideB + 2 * HW + p] : 0.f;

    out[(size_t)b * 3 * HW + p]           = a0 + __ldg(&b5[0]) + b0v;
    out[(size_t)b * 3 * HW + HW + p]      = a1 + __ldg(&b5[1]) + b1v;
    out[(size_t)b * 3 * HW + 2 * HW + p]  = a2 + __ldg(&b5[2]) + b2v;
}

// ---------------------------------------------------------------------------
// host-side helper: one Winograd F(4,3) conv layer (+ fused BN stats)
// ---------------------------------------------------------------------------
static void wino_layer(const float* x, const float* Ubase, const float* bn,
                       float* out, float* V, float* M, float2* part, float* stats,
                       int Cin, int K, int Co, int H, int W)
{
    int tilesW = W >> 2, tilesH = H >> 2;
    int T = 4 * tilesW * tilesH;

    wino_intrans<<<(K * T + 255) / 256, 256>>>(x, bn, V, Cin, K, H, W, tilesW, T);
    dim3 gg(T / 128, Co / 64, 36);
    wino_gemm<<<gg, 256>>>(Ubase, V, M, K, Co, T);
    wino_outtrans<<<Co * T / 256, 256>>>(M, out, part, Co, H, W, tilesW, T);
    bn_finalize<<<1, 256>>>(part, stats, Co, T >> 5, 1.f / (float)(T * 16));
}

// ---------------------------------------------------------------------------
extern "C" void kernel_launch(void* const* d_in, const int* in_sizes, int n_in,
                              void* d_out, int out_size)
{
    const float* f0c = (const float*)d_in[0];
    const float* f1c = (const float*)d_in[1];
    const float* f0f = (const float*)d_in[2];
    const float* f1f = (const float*)d_in[3];
    const float* cw1 = (const float*)d_in[4];
    const float* cw2 = (const float*)d_in[5];
    const float* cw3 = (const float*)d_in[6];
    const float* cw4 = (const float*)d_in[7];
    const float* cw5 = (const float*)d_in[8];
    const float* cb5 = (const float*)d_in[9];
    const float* fw1 = (const float*)d_in[10];
    const float* fw2 = (const float*)d_in[11];
    const float* fw3 = (const float*)d_in[12];
    const float* fw4 = (const float*)d_in[13];
    const float* fw5 = (const float*)d_in[14];
    const float* fb5 = (const float*)d_in[15];

    float *A, *Bb, *V, *M, *U, *warp, *stats;
    float2* part;
    cudaGetSymbolAddress((void**)&A,     g_bufA);
    cudaGetSymbolAddress((void**)&Bb,    g_bufB);
    cudaGetSymbolAddress((void**)&V,     g_V);
    cudaGetSymbolAddress((void**)&M,     g_M);
    cudaGetSymbolAddress((void**)&U,     g_U);
    cudaGetSymbolAddress((void**)&part,  g_bnpart);
    cudaGetSymbolAddress((void**)&warp,  g_warp);
    cudaGetSymbolAddress((void**)&stats, g_stats);

    float* outC = (float*)d_out;                 // (4,3,64,64)
    float* outF = outC + 4 * 3 * 64 * 64;        // (4,3,128,128)

    const int HWc = 64 * 64, HWf = 128 * 128;

    // ---- all weight transforms up front (one kernel) ----
    wino_wtrans_all<<<(249856 + 255) / 256, 256>>>(cw1, cw2, cw3, cw4,
                                                   fw1, fw2, fw3, fw4, U);

    // ---- coarse stage ----
    corr_kernel<<<512, 128>>>(f0c, f1c, warp);

    concat_coarse<<<(4 * 130 * HWc + 255) / 256, 256>>>(f0c, f1c, warp, A);

    wino_layer(A,  U + UO1, nullptr, Bb, V, M, part, stats, 130, 144, 256, 64, 64);
    wino_layer(Bb, U + UO2, stats,   A,  V, M, part, stats, 256, 256, 256, 64, 64);
    wino_layer(A,  U + UO3, stats,   Bb, V, M, part, stats, 256, 256, 256, 64, 64);
    wino_layer(Bb, U + UO4, stats,   A,  V, M, part, stats, 256, 256, 256, 64, 64);

    conv1x1_3_kernel<<<(4 * HWc + 127) / 128, 128>>>(
        A, stats, cw5, cb5, warp, 2, 2 * HWc, outC, 256, HWc, 4);

    // ---- fine stage ----
    upsample2x_kernel<<<(4 * 3 * HWf + 255) / 256, 256>>>(outC, outF, 4, 3, 64, 64);

    concat_fine<<<(4 * 50 * HWf + 255) / 256, 256>>>(f0f, f1f, outF, Bb);

    wino_layer(Bb, U + UF1, nullptr, A,  V, M, part, stats, 50, 64, 64, 128, 128);
    wino_layer(A,  U + UF2, stats,   Bb, V, M, part, stats, 64, 64, 64, 128, 128);
    wino_layer(Bb, U + UF3, stats,   A,  V, M, part, stats, 64, 64, 64, 128, 128);
    wino_layer(A,  U + UF4, stats,   Bb, V, M, part, stats, 64, 64, 64, 128, 128);

    conv1x1_3_kernel<<<(4 * HWf + 127) / 128, 128>>>(
        Bb, stats, fw5, fb5, outF, 3, 3 * HWf, outF, 64, HWf, 4);
}